// round 7
// baseline (speedup 1.0000x reference)
#include <cuda_runtime.h>
#include <cuda_bf16.h>
#include <math.h>
#include <stdint.h>

// ---------------------------------------------------------------------------
// Static device scratch. Activations in (B, E, C) layout: x[(b*E+e)*C + c].
// ---------------------------------------------------------------------------
__device__ float  g_bufA[8388608];
__device__ float  g_bufB[8388608];
__device__ float  g_bufU[4194304];
__device__ float  g_bufY[8388608];
__device__ float  g_wt[400000];      // transposed fp32 weights (conv_small)
__device__ __align__(16) __nv_bfloat16 g_whi[516096];  // fragment-ordered bf16 hi
__device__ __align__(16) __nv_bfloat16 g_wlo[516096];  // fragment-ordered bf16 lo
__device__ double g_stats[1024];
__device__ float2 g_mstat[512];

__device__ __forceinline__ uint32_t smem_u32(const void* p) {
    uint32_t a;
    asm("{ .reg .u64 t; cvta.to.shared.u64 t, %1; cvt.u32.u64 %0, t; }" : "=r"(a) : "l"(p));
    return a;
}
__device__ __forceinline__ uint32_t b2u(__nv_bfloat162 h) {
    return *reinterpret_cast<uint32_t*>(&h);
}

#define STS128(a, r0, r1, r2, r3) \
    asm volatile("st.shared.v4.b32 [%0], {%1, %2, %3, %4};" \
        :: "r"(a), "r"(r0), "r"(r1), "r"(r2), "r"(r3) : "memory")

#define LDMX4(r, addr) \
    asm volatile("ldmatrix.sync.aligned.m8n8.x4.shared.b16 {%0,%1,%2,%3}, [%4];" \
        : "=r"((r)[0]), "=r"((r)[1]), "=r"((r)[2]), "=r"((r)[3]) : "r"(addr))

#define MMA16816(d, a, b0, b1) \
    asm volatile("mma.sync.aligned.m16n8k16.row.col.f32.bf16.bf16.f32 " \
        "{%0,%1,%2,%3}, {%4,%5,%6,%7}, {%8,%9}, {%0,%1,%2,%3};" \
        : "+f"((d)[0]), "+f"((d)[1]), "+f"((d)[2]), "+f"((d)[3]) \
        : "r"((a)[0]), "r"((a)[1]), "r"((a)[2]), "r"((a)[3]), "r"(b0), "r"(b1))

// ---------------------------------------------------------------------------
// fp32 weight transpose (conv_small path; computes all 8, cheap one-off)
// ---------------------------------------------------------------------------
__global__ void wtrans_all(const float* __restrict__ W0, const float* __restrict__ W1,
                           const float* __restrict__ W2, const float* __restrict__ W3,
                           const float* __restrict__ W4, const float* __restrict__ W5,
                           const float* __restrict__ W6, const float* __restrict__ W7,
                           float* __restrict__ wt)
{
    int i = blockIdx.x * 256 + threadIdx.x;
    if (i >= 324160) return;
    const int Ks[8]   = {1280, 640, 640, 320, 320, 160, 160, 40};
    const int Cs[8]   = {128, 128, 64, 64, 32, 32, 8, 8};
    const int offs[9] = {0, 163840, 245760, 286720, 307200, 317440, 322560, 323840, 324160};
    const float* Ws[8] = {W0, W1, W2, W3, W4, W5, W6, W7};
    int seg = 0;
    while (i >= offs[seg + 1]) seg++;
    int j = i - offs[seg];
    int K = Ks[seg], C = Cs[seg];
    int k = j / C, o = j % C;
    wt[i] = Ws[seg][(size_t)o * K + k];
}

// ---------------------------------------------------------------------------
// Fragment-ordered bf16 hi/lo weights for the 6 tensor convs.
// uint4 per (lane): [chunk][na][ka2][lane][reg 0..3][half 0..1]
//   reg0,1 -> B-frag regs of ka = ka2*2;  reg2,3 -> ka2*2+1
//   fragment mapping: n = na*8 + lane/4, kk = ka*16 + (lane%4)*2 + half + rr*8
//   padded k: c = chunk*8 + kk/8, s = kk%8 (s<5 real, else 0)
// ---------------------------------------------------------------------------
__global__ void wbf_frag(const float* __restrict__ W0, const float* __restrict__ W1,
                         const float* __restrict__ W2, const float* __restrict__ W3,
                         const float* __restrict__ W4, const float* __restrict__ W5,
                         __nv_bfloat16* __restrict__ whi, __nv_bfloat16* __restrict__ wlo)
{
    int i = blockIdx.x * 256 + threadIdx.x;
    if (i >= 516096) return;
    const int CINs[6]  = {256, 128, 128, 64, 64, 32};
    const int COUTs[6] = {128, 128, 64, 64, 32, 32};
    const int offs[7]  = {0, 262144, 393216, 458752, 491520, 507904, 516096};
    const float* Ws[6] = {W0, W1, W2, W3, W4, W5};
    int seg = 0;
    while (i >= offs[seg + 1]) seg++;
    int j = i - offs[seg];
    int CIN = CINs[seg], COUT = COUTs[seg];
    int chunk = j / (COUT * 64);
    int r1 = j % (COUT * 64);
    int na   = r1 / 512;
    int r2   = r1 % 512;
    int ka2  = r2 / 256;
    int r3   = r2 % 256;
    int lane = r3 / 8;
    int r4   = r3 % 8;
    int reg  = r4 >> 1, half = r4 & 1;
    int ka = ka2 * 2 + (reg >> 1);
    int rr = reg & 1;
    int n  = na * 8 + lane / 4;
    int kk = ka * 16 + (lane % 4) * 2 + half + rr * 8;
    int c = chunk * 8 + (kk >> 3);
    int s = kk & 7;
    float v = (s < 5) ? Ws[seg][(size_t)n * (CIN * 5) + c * 5 + s] : 0.f;
    __nv_bfloat16 h = __float2bfloat16(v);
    whi[i] = h;
    wlo[i] = __float2bfloat16(v - __bfloat162float(h));
}

__global__ void zero_stats(double* s, int n) {
    int i = blockIdx.x * 256 + threadIdx.x;
    if (i < n) s[i] = 0.0;
}

// ---------------------------------------------------------------------------
// fe (B, C, E) -> (B, E, C) tiled transpose
// ---------------------------------------------------------------------------
__global__ void xpose(const float* __restrict__ in, float* __restrict__ outT,
                      int E, int C) {
    __shared__ float tile[32][33];
    int bb = blockIdx.z;
    int e0 = blockIdx.x * 32, c0 = blockIdx.y * 32;
    int tx = threadIdx.x, ty = threadIdx.y;          // (32, 8)
    const float* inb = in + (size_t)bb * C * E;
    float* ob = outT + (size_t)bb * E * C;
#pragma unroll
    for (int j = 0; j < 32; j += 8)
        tile[ty + j][tx] = inb[(size_t)(c0 + ty + j) * E + e0 + tx];
    __syncthreads();
#pragma unroll
    for (int j = 0; j < 32; j += 8)
        ob[(size_t)(e0 + ty + j) * C + c0 + tx] = tile[tx][ty + j];
}

// ---------------------------------------------------------------------------
// Tensor-core mesh conv via mma.sync (m16n8k16 bf16, fp32 accum).
// Block: 128 edges x COUT. 256 threads = 8 warps: wm = wid&3 (32 rows each),
// wn = wid>>2 (2 N-groups). Split precision: AhBh + AlBh + AhBl.
// K padded: channel -> 8 k-slots (5 real). Chunk = 8 channels = 64 k.
// ---------------------------------------------------------------------------
template<int CIN, int COUT>
__global__ __launch_bounds__(256) void conv_t(
    const float* __restrict__ x, const int4* __restrict__ gemm,
    const __nv_bfloat16* __restrict__ Whi, const __nv_bfloat16* __restrict__ Wlo,
    const float* __restrict__ bias, float* __restrict__ out, int E)
{
    constexpr int CHUNKS = CIN / 8;
    constexpr int NA = COUT / 16;          // n-atoms per warp (2 N-groups)
    constexpr int PITCH = 144;             // A row pitch (bytes), conflict-free

    __shared__ __align__(16) uint8_t sAhi[128 * PITCH];
    __shared__ __align__(16) uint8_t sAlo[128 * PITCH];
    __shared__ int4 sIdx[128];

    const int tid = threadIdx.x;
    const int wid = tid >> 5, lane = tid & 31;
    const int wm = wid & 3, wn = wid >> 2;
    const int bb = blockIdx.y;
    const int e0 = blockIdx.x * 128;
    const float* xb = x + (size_t)bb * E * CIN;

    const uint32_t sAhiU = smem_u32(sAhi);
    const uint32_t sAloU = smem_u32(sAlo);

    for (int i = tid; i < 128; i += 256) sIdx[i] = gemm[e0 + i];

    const int cc = tid & 7;        // channel-in-chunk
    const int elb = tid >> 3;      // edge base (0..31), items at elb+32q

    float acc[2][NA][4];
#pragma unroll
    for (int ma = 0; ma < 2; ma++)
#pragma unroll
        for (int na = 0; na < NA; na++)
#pragma unroll
            for (int u = 0; u < 4; u++) acc[ma][na][u] = 0.f;

    const uint4* bh4 = reinterpret_cast<const uint4*>(Whi);
    const uint4* bl4 = reinterpret_cast<const uint4*>(Wlo);

    __syncthreads();

    for (int chunk = 0; chunk < CHUNKS; chunk++) {
        // ---- gather + convert + STS (A hi/lo) ----
        {
            const float* xc = xb + chunk * 8 + cc;
#pragma unroll
            for (int q = 0; q < 4; q++) {
                int el = elb + 32 * q;
                int4 n = sIdx[el];
                float xe = xc[(size_t)(e0 + el) * CIN];
                float f1 = xc[(size_t)n.x * CIN];
                float f2 = xc[(size_t)n.y * CIN];
                float f3 = xc[(size_t)n.z * CIN];
                float f4 = xc[(size_t)n.w * CIN];
                float g0 = xe;
                float g1 = f1 + f3, g2 = f2 + f4;
                float g3 = fabsf(f1 - f3), g4 = fabsf(f2 - f4);
                __nv_bfloat16 h0 = __float2bfloat16(g0);
                __nv_bfloat16 h1 = __float2bfloat16(g1);
                __nv_bfloat16 h2 = __float2bfloat16(g2);
                __nv_bfloat16 h3 = __float2bfloat16(g3);
                __nv_bfloat16 h4 = __float2bfloat16(g4);
                float r0 = g0 - __bfloat162float(h0);
                float r1 = g1 - __bfloat162float(h1);
                float r2 = g2 - __bfloat162float(h2);
                float r3 = g3 - __bfloat162float(h3);
                float r4 = g4 - __bfloat162float(h4);
                uint32_t off = (uint32_t)el * PITCH + (uint32_t)cc * 16;
                __nv_bfloat16 z = __float2bfloat16(0.f);
                STS128(sAhiU + off,
                       b2u(__halves2bfloat162(h0, h1)),
                       b2u(__halves2bfloat162(h2, h3)),
                       b2u(__halves2bfloat162(h4, z)), 0u);
                STS128(sAloU + off,
                       b2u(__floats2bfloat162_rn(r0, r1)),
                       b2u(__floats2bfloat162_rn(r2, r3)),
                       b2u(__floats2bfloat162_rn(r4, 0.f)), 0u);
            }
        }
        __syncthreads();
        // ---- ldmatrix + mma ----
#pragma unroll
        for (int ka2 = 0; ka2 < 2; ka2++) {
            uint32_t ah[2][2][4], al[2][2][4];
#pragma unroll
            for (int ma = 0; ma < 2; ma++)
#pragma unroll
                for (int ks = 0; ks < 2; ks++) {
                    uint32_t off = (uint32_t)(wm * 32 + ma * 16 + (lane & 15)) * PITCH
                                 + (uint32_t)(ka2 * 2 + ks) * 32 + ((lane >> 4) * 16);
                    LDMX4(ah[ma][ks], sAhiU + off);
                    LDMX4(al[ma][ks], sAloU + off);
                }
#pragma unroll
            for (int na = 0; na < NA; na++) {
                int gi = ((chunk * (COUT / 8) + wn * NA + na) * 2 + ka2) * 32 + lane;
                uint4 bh = bh4[gi];
                uint4 bl = bl4[gi];
#pragma unroll
                for (int ma = 0; ma < 2; ma++) {
                    MMA16816(acc[ma][na], ah[ma][0], bh.x, bh.y);
                    MMA16816(acc[ma][na], al[ma][0], bh.x, bh.y);
                    MMA16816(acc[ma][na], ah[ma][0], bl.x, bl.y);
                    MMA16816(acc[ma][na], ah[ma][1], bh.z, bh.w);
                    MMA16816(acc[ma][na], al[ma][1], bh.z, bh.w);
                    MMA16816(acc[ma][na], ah[ma][1], bl.z, bl.w);
                }
            }
        }
        __syncthreads();
    }

    // ---- epilogue: acc + bias -> out ----
    const int rbase = e0 + wm * 32 + (lane >> 2);
#pragma unroll
    for (int ma = 0; ma < 2; ma++) {
#pragma unroll
        for (int na = 0; na < NA; na++) {
            int col = wn * NA * 8 + na * 8 + (lane & 3) * 2;
            float bx = bias[col], by = bias[col + 1];
            int row0 = rbase + ma * 16;
            float* p0 = out + ((size_t)bb * E + row0) * COUT + col;
            float* p1 = p0 + (size_t)8 * COUT;
            *reinterpret_cast<float2*>(p0) =
                make_float2(acc[ma][na][0] + bx, acc[ma][na][1] + by);
            *reinterpret_cast<float2*>(p1) =
                make_float2(acc[ma][na][2] + bx, acc[ma][na][3] + by);
        }
    }
}

// ---------------------------------------------------------------------------
// Small-Cout mesh-conv (COUT = 8), fp32
// ---------------------------------------------------------------------------
template<int CIN>
__global__ __launch_bounds__(256) void conv_small(
    const float* __restrict__ x, const int4* __restrict__ gemm,
    const float* __restrict__ Wt, const float* __restrict__ bias,
    float* __restrict__ out, int E)
{
    constexpr int K = CIN * 5;
    __shared__ float sW[K * 8];
    int tid = threadIdx.x;
    for (int i = tid; i < K * 8; i += 256) sW[i] = Wt[i];
    float acc[8];
#pragma unroll
    for (int o = 0; o < 8; o++) acc[o] = bias[o];
    __syncthreads();

    int bb = blockIdx.y;
    int e = blockIdx.x * 256 + tid;
    int4 n = gemm[e];
    const float* xb = x + (size_t)bb * E * CIN;
    const float4* r0 = reinterpret_cast<const float4*>(xb + (size_t)e * CIN);
    const float4* r1 = reinterpret_cast<const float4*>(xb + (size_t)n.x * CIN);
    const float4* r2 = reinterpret_cast<const float4*>(xb + (size_t)n.y * CIN);
    const float4* r3 = reinterpret_cast<const float4*>(xb + (size_t)n.z * CIN);
    const float4* r4 = reinterpret_cast<const float4*>(xb + (size_t)n.w * CIN);

#pragma unroll 2
    for (int c4 = 0; c4 < CIN / 4; c4++) {
        float4 xe = r0[c4], a1 = r1[c4], a2 = r2[c4], a3 = r3[c4], a4 = r4[c4];
#define PROC(COMP, CC)                                                         \
        {                                                                      \
            float g0 = xe.COMP;                                                \
            float s1 = a1.COMP + a3.COMP;                                      \
            float s2 = a2.COMP + a4.COMP;                                      \
            float d1 = fabsf(a1.COMP - a3.COMP);                               \
            float d2 = fabsf(a2.COMP - a4.COMP);                               \
            const float* w = &sW[(c4 * 4 + CC) * 5 * 8];                       \
            for (int o = 0; o < 8; o++)                                       \
                acc[o] += g0 * w[o] + s1 * w[8 + o] + s2 * w[16 + o]           \
                        + d1 * w[24 + o] + d2 * w[32 + o];                     \
        }
        PROC(x, 0) PROC(y, 1) PROC(z, 2) PROC(w, 3)
#undef PROC
    }
    float* po = out + ((size_t)bb * E + e) * 8;
    *reinterpret_cast<float4*>(po)     = make_float4(acc[0], acc[1], acc[2], acc[3]);
    *reinterpret_cast<float4*>(po + 4) = make_float4(acc[4], acc[5], acc[6], acc[7]);
}

// ---------------------------------------------------------------------------
// unpool + skip
// ---------------------------------------------------------------------------
template<int C>
__global__ __launch_bounds__(256) void unpool_skip(
    const float* __restrict__ up, const int* __restrict__ unpool,
    const float* __restrict__ skip, float* __restrict__ out,
    int Eout, int Ein)
{
    constexpr int TE = 32;
    __shared__ float ssk[C][TE + 1];
    __shared__ int su[TE];
    int tid = threadIdx.x;
    int bb = blockIdx.y;
    int e0 = blockIdx.x * TE;
    if (tid < TE) su[tid] = unpool[e0 + tid];
    const float* skb = skip + (size_t)bb * C * Eout;
    for (int i = tid; i < C * TE; i += 256) {
        int c = i >> 5, e = i & 31;
        ssk[c][e] = skb[(size_t)c * Eout + e0 + e];
    }
    __syncthreads();
    const float* upb = up + (size_t)bb * Ein * C;
    float* ob = out + ((size_t)bb * Eout + e0) * C;
    for (int i = tid; i < C * TE; i += 256) {
        int el = i / C, c = i % C;
        ob[(size_t)el * C + c] = upb[(size_t)su[el] * C + c] + ssk[c][el];
    }
}

// ---------------------------------------------------------------------------
// Instance norm
// ---------------------------------------------------------------------------
template<int C, int CHUNK>
__global__ __launch_bounds__(256) void inorm_partial(
    const float* __restrict__ x, int E, double* __restrict__ stats)
{
    constexpr int C4 = C / 4;
    constexpr int ESTEP = 256 / C4;
    __shared__ float rb[256][8];
    int tid = threadIdx.x;
    int c4 = tid % C4, er = tid / C4;
    int bb = blockIdx.z;
    int e0 = blockIdx.x * CHUNK;
    const float4* xb4 = reinterpret_cast<const float4*>(x + ((size_t)bb * E + e0) * C) + c4;
    float s0 = 0, s1 = 0, s2 = 0, s3 = 0, q0 = 0, q1 = 0, q2 = 0, q3 = 0;
    for (int e = er; e < CHUNK; e += ESTEP) {
        float4 v = xb4[(size_t)e * C4];
        s0 += v.x; q0 += v.x * v.x;
        s1 += v.y; q1 += v.y * v.y;
        s2 += v.z; q2 += v.z * v.z;
        s3 += v.w; q3 += v.w * v.w;
    }
    rb[tid][0] = s0; rb[tid][1] = s1; rb[tid][2] = s2; rb[tid][3] = s3;
    rb[tid][4] = q0; rb[tid][5] = q1; rb[tid][6] = q2; rb[tid][7] = q3;
    __syncthreads();
    for (int st = ESTEP / 2; st >= 1; st >>= 1) {
        if (er < st) {
#pragma unroll
            for (int u = 0; u < 8; u++) rb[tid][u] += rb[tid + st * C4][u];
        }
        __syncthreads();
    }
    if (er == 0) {
#pragma unroll
        for (int u = 0; u < 4; u++) {
            atomicAdd(&stats[((size_t)bb * C + c4 * 4 + u) * 2],     (double)rb[tid][u]);
            atomicAdd(&stats[((size_t)bb * C + c4 * 4 + u) * 2 + 1], (double)rb[tid][4 + u]);
        }
    }
}

__global__ void finalize_stats(const double* __restrict__ stats,
                               float2* __restrict__ mstat, int n, int E)
{
    int i = threadIdx.x;
    if (i >= n) return;
    double invE = 1.0 / (double)E;
    double m = stats[2 * i] * invE;
    double var = stats[2 * i + 1] * invE - m * m;
    mstat[i] = make_float2((float)m, rsqrtf((float)var + 1e-5f));
}

template<int C>
__global__ __launch_bounds__(256) void inorm_apply(
    float* __restrict__ x, int E, const float2* __restrict__ mstat)
{
    int idx = blockIdx.x * 256 + threadIdx.x;
    int c = idx % C;
    int bb = idx / (E * C);
    float2 mr = mstat[bb * C + c];
    float v = (x[idx] - mr.x) * mr.y;
    x[idx] = v > 0.f ? v : 0.f;
}

__global__ __launch_bounds__(256) void inorm_apply_final(
    const float* __restrict__ x, int E, const float2* __restrict__ mstat,
    float* __restrict__ out)
{
    __shared__ float sm[256];
    int tid = threadIdx.x;
    int bb = blockIdx.y;
    int e0 = blockIdx.x * 32;
    float2 mr = mstat[bb * 8 + (tid & 7)];
    float v = (x[((size_t)bb * E + e0) * 8 + tid] - mr.x) * mr.y;
    sm[tid] = v > 0.f ? v : 0.f;
    __syncthreads();
    int c = tid >> 5, el = tid & 31;
    out[((size_t)bb * 8 + c) * E + e0 + el] = sm[el * 8 + c];
}

// ---------------------------------------------------------------------------
// Host driver
// ---------------------------------------------------------------------------
extern "C" void kernel_launch(void* const* d_in, const int* in_sizes, int n_in,
                              void* d_out, int out_size)
{
    (void)in_sizes; (void)n_in; (void)out_size;
    const int E0 = 16384, E1 = 32768, E2 = 65536, E3 = 131072;

    const float* fe    = (const float*)d_in[0];
    const float* skip0 = (const float*)d_in[1];
    const float* skip1 = (const float*)d_in[2];
    const float* skip2 = (const float*)d_in[3];
    const int4*  gm0   = (const int4*)d_in[4];
    const int4*  gm1   = (const int4*)d_in[5];
    const int4*  gm2   = (const int4*)d_in[6];
    const int4*  gm3   = (const int4*)d_in[7];
    const int*   up0   = (const int*)d_in[8];
    const int*   up1   = (const int*)d_in[9];
    const int*   up2   = (const int*)d_in[10];
    const float* Wup0 = (const float*)d_in[11]; const float* bup0 = (const float*)d_in[12];
    const float* Wc0  = (const float*)d_in[13]; const float* bc0  = (const float*)d_in[14];
    const float* Wup1 = (const float*)d_in[15]; const float* bup1 = (const float*)d_in[16];
    const float* Wc1  = (const float*)d_in[17]; const float* bc1  = (const float*)d_in[18];
    const float* Wup2 = (const float*)d_in[19]; const float* bup2 = (const float*)d_in[20];
    const float* Wc2  = (const float*)d_in[21]; const float* bc2  = (const float*)d_in[22];
    const float* Wupf = (const float*)d_in[23]; const float* bupf = (const float*)d_in[24];
    const float* Wcf  = (const float*)d_in[25]; const float* bcf  = (const float*)d_in[26];
    float* outp = (float*)d_out;

    float *bufA, *bufB, *bufU, *bufY, *wt; double* stats; float2* mstat;
    __nv_bfloat16 *whi, *wlo;
    cudaGetSymbolAddress((void**)&bufA, g_bufA);
    cudaGetSymbolAddress((void**)&bufB, g_bufB);
    cudaGetSymbolAddress((void**)&bufU, g_bufU);
    cudaGetSymbolAddress((void**)&bufY, g_bufY);
    cudaGetSymbolAddress((void**)&wt,   g_wt);
    cudaGetSymbolAddress((void**)&whi,  g_whi);
    cudaGetSymbolAddress((void**)&wlo,  g_wlo);
    cudaGetSymbolAddress((void**)&stats, g_stats);
    cudaGetSymbolAddress((void**)&mstat, g_mstat);

    float* Wt_upf = wt + 322560;
    float* Wt_cf  = wt + 323840;

    __nv_bfloat16* Whi_up0 = whi;            __nv_bfloat16* Wlo_up0 = wlo;
    __nv_bfloat16* Whi_c0  = whi + 262144;   __nv_bfloat16* Wlo_c0  = wlo + 262144;
    __nv_bfloat16* Whi_up1 = whi + 393216;   __nv_bfloat16* Wlo_up1 = wlo + 393216;
    __nv_bfloat16* Whi_c1  = whi + 458752;   __nv_bfloat16* Wlo_c1  = wlo + 458752;
    __nv_bfloat16* Whi_up2 = whi + 491520;   __nv_bfloat16* Wlo_up2 = wlo + 491520;
    __nv_bfloat16* Whi_c2  = whi + 507904;   __nv_bfloat16* Wlo_c2  = wlo + 507904;

    double* stats0 = stats;
    double* stats1 = stats + 512;
    double* stats2 = stats + 768;
    double* statsF = stats + 896;
    float2* mst0 = mstat;
    float2* mst1 = mstat + 256;
    float2* mst2 = mstat + 384;
    float2* mstF = mstat + 448;

    // launches 0-4 (setup), launch 5 = conv_t up0 (ncu target)
    wtrans_all<<<1267, 256>>>(Wup0, Wc0, Wup1, Wc1, Wup2, Wc2, Wupf, Wcf, wt);
    wbf_frag<<<2016, 256>>>(Wup0, Wc0, Wup1, Wc1, Wup2, Wc2, whi, wlo);
    zero_stats<<<2, 256>>>(stats, 512);
    zero_stats<<<2, 256>>>(stats + 512, 512);
    xpose<<<dim3(E0 / 32, 256 / 32, 2), dim3(32, 8)>>>(fe, bufA, E0, 256);

    // ---- Level 0 ----
    conv_t<256, 128><<<dim3(E0 / 128, 2), 256>>>(bufA, gm0, Whi_up0, Wlo_up0, bup0, bufU, E0);
    unpool_skip<128><<<dim3(E1 / 32, 2), 256>>>(bufU, up0, skip0, bufY, E1, E0);
    conv_t<128, 128><<<dim3(E1 / 128, 2), 256>>>(bufY, gm1, Whi_c0, Wlo_c0, bc0, bufB, E1);
    inorm_partial<128, 256><<<dim3(E1 / 256, 1, 2), 256>>>(bufB, E1, stats0);
    finalize_stats<<<1, 256>>>(stats0, mst0, 256, E1);
    inorm_apply<128><<<(2 * E1 * 128) / 256, 256>>>(bufB, E1, mst0);

    // ---- Level 1 ----
    conv_t<128, 64><<<dim3(E1 / 128, 2), 256>>>(bufB, gm1, Whi_up1, Wlo_up1, bup1, bufU, E1);
    unpool_skip<64><<<dim3(E2 / 32, 2), 256>>>(bufU, up1, skip1, bufY, E2, E1);
    conv_t<64, 64><<<dim3(E2 / 128, 2), 256>>>(bufY, gm2, Whi_c1, Wlo_c1, bc1, bufA, E2);
    inorm_partial<64, 512><<<dim3(E2 / 512, 1, 2), 256>>>(bufA, E2, stats1);
    finalize_stats<<<1, 128>>>(stats1, mst1, 128, E2);
    inorm_apply<64><<<(2 * E2 * 64) / 256, 256>>>(bufA, E2, mst1);

    // ---- Level 2 ----
    conv_t<64, 32><<<dim3(E2 / 128, 2), 256>>>(bufA, gm2, Whi_up2, Wlo_up2, bup2, bufU, E2);
    unpool_skip<32><<<dim3(E3 / 32, 2), 256>>>(bufU, up2, skip2, bufY, E3, E2);
    conv_t<32, 32><<<dim3(E3 / 128, 2), 256>>>(bufY, gm3, Whi_c2, Wlo_c2, bc2, bufB, E3);
    inorm_partial<32, 1024><<<dim3(E3 / 1024, 1, 2), 256>>>(bufB, E3, stats2);
    finalize_stats<<<1, 64>>>(stats2, mst2, 64, E3);
    inorm_apply<32><<<(2 * E3 * 32) / 256, 256>>>(bufB, E3, mst2);

    // ---- Final ----
    conv_small<32><<<dim3(E3 / 256, 2), 256>>>(bufB, gm3, Wt_upf, bupf, bufU, E3);
    conv_small<8><<<dim3(E3 / 256, 2), 256>>>(bufU, gm3, Wt_cf, bcf, bufY, E3);
    inorm_partial<8, 4096><<<dim3(E3 / 4096, 1, 2), 256>>>(bufY, E3, statsF);
    finalize_stats<<<1, 16>>>(statsF, mstF, 16, E3);
    inorm_apply_final<<<dim3(E3 / 32, 2), 256>>>(bufY, E3, mstF, outp);
}

// round 8
// speedup vs baseline: 1.7298x; 1.7298x over previous
#include <cuda_runtime.h>
#include <cuda_bf16.h>
#include <math.h>
#include <stdint.h>

// ---------------------------------------------------------------------------
// Static device scratch. Activations in (B, E, C) layout: x[(b*E+e)*C + c].
// ---------------------------------------------------------------------------
__device__ float  g_bufA[8388608];
__device__ float  g_bufB[8388608];
__device__ float  g_bufU[4194304];
__device__ float  g_bufY[8388608];
__device__ float  g_wt[400000];      // transposed fp32 weights (conv_small)
__device__ __align__(16) __nv_bfloat16 g_whi[516096];  // fragment-ordered bf16 hi
__device__ __align__(16) __nv_bfloat16 g_wlo[516096];  // fragment-ordered bf16 lo
__device__ double g_stats[1024];
__device__ float2 g_mstat[512];

__device__ __forceinline__ uint32_t smem_u32(const void* p) {
    uint32_t a;
    asm("{ .reg .u64 t; cvta.to.shared.u64 t, %1; cvt.u32.u64 %0, t; }" : "=r"(a) : "l"(p));
    return a;
}
__device__ __forceinline__ uint32_t b2u(__nv_bfloat162 h) {
    return *reinterpret_cast<uint32_t*>(&h);
}

#define STS128(a, r0, r1, r2, r3) \
    asm volatile("st.shared.v4.b32 [%0], {%1, %2, %3, %4};" \
        :: "r"(a), "r"(r0), "r"(r1), "r"(r2), "r"(r3) : "memory")

#define LDMX4(r, addr) \
    asm volatile("ldmatrix.sync.aligned.m8n8.x4.shared.b16 {%0,%1,%2,%3}, [%4];" \
        : "=r"((r)[0]), "=r"((r)[1]), "=r"((r)[2]), "=r"((r)[3]) : "r"(addr))

#define MMA16816(d, a, b0, b1) \
    asm volatile("mma.sync.aligned.m16n8k16.row.col.f32.bf16.bf16.f32 " \
        "{%0,%1,%2,%3}, {%4,%5,%6,%7}, {%8,%9}, {%0,%1,%2,%3};" \
        : "+f"((d)[0]), "+f"((d)[1]), "+f"((d)[2]), "+f"((d)[3]) \
        : "r"((a)[0]), "r"((a)[1]), "r"((a)[2]), "r"((a)[3]), "r"(b0), "r"(b1))

// ---------------------------------------------------------------------------
// fp32 weight transpose (conv_small path) + stats zeroing (fused)
// ---------------------------------------------------------------------------
__global__ void wtrans_all(const float* __restrict__ W0, const float* __restrict__ W1,
                           const float* __restrict__ W2, const float* __restrict__ W3,
                           const float* __restrict__ W4, const float* __restrict__ W5,
                           const float* __restrict__ W6, const float* __restrict__ W7,
                           float* __restrict__ wt, double* __restrict__ stats)
{
    int i = blockIdx.x * 256 + threadIdx.x;
    if (i < 1024) stats[i] = 0.0;
    if (i >= 324160) return;
    const int Ks[8]   = {1280, 640, 640, 320, 320, 160, 160, 40};
    const int Cs[8]   = {128, 128, 64, 64, 32, 32, 8, 8};
    const int offs[9] = {0, 163840, 245760, 286720, 307200, 317440, 322560, 323840, 324160};
    const float* Ws[8] = {W0, W1, W2, W3, W4, W5, W6, W7};
    int seg = 0;
    while (i >= offs[seg + 1]) seg++;
    int j = i - offs[seg];
    int K = Ks[seg], C = Cs[seg];
    int k = j / C, o = j % C;
    wt[i] = Ws[seg][(size_t)o * K + k];
}

// ---------------------------------------------------------------------------
// Fragment-ordered bf16 hi/lo weights for the 6 tensor convs (verified R7).
// ---------------------------------------------------------------------------
__global__ void wbf_frag(const float* __restrict__ W0, const float* __restrict__ W1,
                         const float* __restrict__ W2, const float* __restrict__ W3,
                         const float* __restrict__ W4, const float* __restrict__ W5,
                         __nv_bfloat16* __restrict__ whi, __nv_bfloat16* __restrict__ wlo)
{
    int i = blockIdx.x * 256 + threadIdx.x;
    if (i >= 516096) return;
    const int CINs[6]  = {256, 128, 128, 64, 64, 32};
    const int COUTs[6] = {128, 128, 64, 64, 32, 32};
    const int offs[7]  = {0, 262144, 393216, 458752, 491520, 507904, 516096};
    const float* Ws[6] = {W0, W1, W2, W3, W4, W5};
    int seg = 0;
    while (i >= offs[seg + 1]) seg++;
    int j = i - offs[seg];
    int CIN = CINs[seg], COUT = COUTs[seg];
    int chunk = j / (COUT * 64);
    int r1 = j % (COUT * 64);
    int na   = r1 / 512;
    int r2   = r1 % 512;
    int ka2  = r2 / 256;
    int r3   = r2 % 256;
    int lane = r3 / 8;
    int r4   = r3 % 8;
    int reg  = r4 >> 1, half = r4 & 1;
    int ka = ka2 * 2 + (reg >> 1);
    int rr = reg & 1;
    int n  = na * 8 + lane / 4;
    int kk = ka * 16 + (lane % 4) * 2 + half + rr * 8;
    int c = chunk * 8 + (kk >> 3);
    int s = kk & 7;
    float v = (s < 5) ? Ws[seg][(size_t)n * (CIN * 5) + c * 5 + s] : 0.f;
    __nv_bfloat16 h = __float2bfloat16(v);
    whi[i] = h;
    wlo[i] = __float2bfloat16(v - __bfloat162float(h));
}

// ---------------------------------------------------------------------------
// fe (B, C, E) -> (B, E, C) tiled transpose
// ---------------------------------------------------------------------------
__global__ void xpose(const float* __restrict__ in, float* __restrict__ outT,
                      int E, int C) {
    __shared__ float tile[32][33];
    int bb = blockIdx.z;
    int e0 = blockIdx.x * 32, c0 = blockIdx.y * 32;
    int tx = threadIdx.x, ty = threadIdx.y;          // (32, 8)
    const float* inb = in + (size_t)bb * C * E;
    float* ob = outT + (size_t)bb * E * C;
#pragma unroll
    for (int j = 0; j < 32; j += 8)
        tile[ty + j][tx] = inb[(size_t)(c0 + ty + j) * E + e0 + tx];
    __syncthreads();
#pragma unroll
    for (int j = 0; j < 32; j += 8)
        ob[(size_t)(e0 + ty + j) * C + c0 + tx] = tile[tx][ty + j];
}

// ---------------------------------------------------------------------------
// Tensor-core mesh conv (m16n8k16 bf16 mma.sync), double-buffered A tiles +
// register-prefetched gathers: one sync per chunk, gather latency hidden
// behind the previous chunk's ldmatrix+mma.
// ---------------------------------------------------------------------------
template<int CIN, int COUT>
__global__ __launch_bounds__(256, 2) void conv_t(
    const float* __restrict__ x, const int4* __restrict__ gemm,
    const __nv_bfloat16* __restrict__ Whi, const __nv_bfloat16* __restrict__ Wlo,
    const float* __restrict__ bias, float* __restrict__ out, int E)
{
    constexpr int CHUNKS = CIN / 8;
    constexpr int NA = COUT / 16;
    constexpr int PITCH = 144;
    constexpr int ABUF = 128 * PITCH;   // one A tile (hi or lo): 18432 B

    extern __shared__ char smem_raw[];
    const uint32_t sAU = smem_u32(smem_raw);     // 4 tiles: [buf][hi/lo]
    int4* sIdx = reinterpret_cast<int4*>(smem_raw + 4 * ABUF);

    const int tid = threadIdx.x;
    const int wid = tid >> 5, lane = tid & 31;
    const int wm = wid & 3, wn = wid >> 2;
    const int bb = blockIdx.y;
    const int e0 = blockIdx.x * 128;
    const float* xb = x + (size_t)bb * E * CIN;

    for (int i = tid; i < 128; i += 256) sIdx[i] = gemm[e0 + i];

    const int cc = tid & 7;        // channel-in-chunk
    const int elb = tid >> 3;      // edge base (0..31), items at elb+32q

    float acc[2][NA][4];
#pragma unroll
    for (int ma = 0; ma < 2; ma++)
#pragma unroll
        for (int na = 0; na < NA; na++)
#pragma unroll
            for (int u = 0; u < 4; u++) acc[ma][na][u] = 0.f;

    const uint4* bh4 = reinterpret_cast<const uint4*>(Whi);
    const uint4* bl4 = reinterpret_cast<const uint4*>(Wlo);

    __syncthreads();   // sIdx ready

    float g[4][5];
    auto gather = [&](int chunk) {
        const float* xc = xb + chunk * 8 + cc;
#pragma unroll
        for (int q = 0; q < 4; q++) {
            int el = elb + 32 * q;
            int4 n = sIdx[el];
            float xe = xc[(size_t)(e0 + el) * CIN];
            float f1 = xc[(size_t)n.x * CIN];
            float f2 = xc[(size_t)n.y * CIN];
            float f3 = xc[(size_t)n.z * CIN];
            float f4 = xc[(size_t)n.w * CIN];
            g[q][0] = xe;
            g[q][1] = f1 + f3;  g[q][2] = f2 + f4;
            g[q][3] = fabsf(f1 - f3);  g[q][4] = fabsf(f2 - f4);
        }
    };

    gather(0);

    for (int chunk = 0; chunk < CHUNKS; chunk++) {
        const uint32_t bufHi = sAU + (uint32_t)((chunk & 1) * 2) * ABUF;
        const uint32_t bufLo = bufHi + ABUF;
        // ---- commit prefetched gathers to A tiles ----
#pragma unroll
        for (int q = 0; q < 4; q++) {
            int el = elb + 32 * q;
            uint32_t off = (uint32_t)el * PITCH + (uint32_t)cc * 16;
            __nv_bfloat16 h0 = __float2bfloat16(g[q][0]);
            __nv_bfloat16 h1 = __float2bfloat16(g[q][1]);
            __nv_bfloat16 h2 = __float2bfloat16(g[q][2]);
            __nv_bfloat16 h3 = __float2bfloat16(g[q][3]);
            __nv_bfloat16 h4 = __float2bfloat16(g[q][4]);
            float r0 = g[q][0] - __bfloat162float(h0);
            float r1 = g[q][1] - __bfloat162float(h1);
            float r2 = g[q][2] - __bfloat162float(h2);
            float r3 = g[q][3] - __bfloat162float(h3);
            float r4 = g[q][4] - __bfloat162float(h4);
            __nv_bfloat16 z = __float2bfloat16(0.f);
            STS128(bufHi + off,
                   b2u(__halves2bfloat162(h0, h1)),
                   b2u(__halves2bfloat162(h2, h3)),
                   b2u(__halves2bfloat162(h4, z)), 0u);
            STS128(bufLo + off,
                   b2u(__floats2bfloat162_rn(r0, r1)),
                   b2u(__floats2bfloat162_rn(r2, r3)),
                   b2u(__floats2bfloat162_rn(r4, 0.f)), 0u);
        }
        __syncthreads();
        // ---- prefetch next chunk's gathers (latency hidden by mma below) ----
        if (chunk + 1 < CHUNKS) gather(chunk + 1);
        // ---- ldmatrix + mma from current buffers ----
#pragma unroll
        for (int ka2 = 0; ka2 < 2; ka2++) {
            uint32_t ah[2][2][4], al[2][2][4];
#pragma unroll
            for (int ma = 0; ma < 2; ma++)
#pragma unroll
                for (int ks = 0; ks < 2; ks++) {
                    uint32_t off = (uint32_t)(wm * 32 + ma * 16 + (lane & 15)) * PITCH
                                 + (uint32_t)(ka2 * 2 + ks) * 32 + ((lane >> 4) * 16);
                    LDMX4(ah[ma][ks], bufHi + off);
                    LDMX4(al[ma][ks], bufLo + off);
                }
#pragma unroll
            for (int na = 0; na < NA; na++) {
                int gi = ((chunk * (COUT / 8) + wn * NA + na) * 2 + ka2) * 32 + lane;
                uint4 bh = bh4[gi];
                uint4 bl = bl4[gi];
#pragma unroll
                for (int ma = 0; ma < 2; ma++) {
                    MMA16816(acc[ma][na], ah[ma][0], bh.x, bh.y);
                    MMA16816(acc[ma][na], al[ma][0], bh.x, bh.y);
                    MMA16816(acc[ma][na], ah[ma][0], bl.x, bl.y);
                    MMA16816(acc[ma][na], ah[ma][1], bh.z, bh.w);
                    MMA16816(acc[ma][na], al[ma][1], bh.z, bh.w);
                    MMA16816(acc[ma][na], ah[ma][1], bl.z, bl.w);
                }
            }
        }
    }

    // ---- epilogue: acc + bias -> out ----
    const int rbase = e0 + wm * 32 + (lane >> 2);
#pragma unroll
    for (int ma = 0; ma < 2; ma++) {
#pragma unroll
        for (int na = 0; na < NA; na++) {
            int col = wn * NA * 8 + na * 8 + (lane & 3) * 2;
            float bx = bias[col], by = bias[col + 1];
            int row0 = rbase + ma * 16;
            float* p0 = out + ((size_t)bb * E + row0) * COUT + col;
            float* p1 = p0 + (size_t)8 * COUT;
            *reinterpret_cast<float2*>(p0) =
                make_float2(acc[ma][na][0] + bx, acc[ma][na][1] + by);
            *reinterpret_cast<float2*>(p1) =
                make_float2(acc[ma][na][2] + bx, acc[ma][na][3] + by);
        }
    }
}

// ---------------------------------------------------------------------------
// Small-Cout mesh-conv (COUT = 8), fp32
// ---------------------------------------------------------------------------
template<int CIN>
__global__ __launch_bounds__(256) void conv_small(
    const float* __restrict__ x, const int4* __restrict__ gemm,
    const float* __restrict__ Wt, const float* __restrict__ bias,
    float* __restrict__ out, int E)
{
    constexpr int K = CIN * 5;
    __shared__ float sW[K * 8];
    int tid = threadIdx.x;
    for (int i = tid; i < K * 8; i += 256) sW[i] = Wt[i];
    float acc[8];
#pragma unroll
    for (int o = 0; o < 8; o++) acc[o] = bias[o];
    __syncthreads();

    int bb = blockIdx.y;
    int e = blockIdx.x * 256 + tid;
    int4 n = gemm[e];
    const float* xb = x + (size_t)bb * E * CIN;
    const float4* r0 = reinterpret_cast<const float4*>(xb + (size_t)e * CIN);
    const float4* r1 = reinterpret_cast<const float4*>(xb + (size_t)n.x * CIN);
    const float4* r2 = reinterpret_cast<const float4*>(xb + (size_t)n.y * CIN);
    const float4* r3 = reinterpret_cast<const float4*>(xb + (size_t)n.z * CIN);
    const float4* r4 = reinterpret_cast<const float4*>(xb + (size_t)n.w * CIN);

#pragma unroll 2
    for (int c4 = 0; c4 < CIN / 4; c4++) {
        float4 xe = r0[c4], a1 = r1[c4], a2 = r2[c4], a3 = r3[c4], a4 = r4[c4];
#define PROC(COMP, CC)                                                         \
        {                                                                      \
            float g0 = xe.COMP;                                                \
            float s1 = a1.COMP + a3.COMP;                                      \
            float s2 = a2.COMP + a4.COMP;                                      \
            float d1 = fabsf(a1.COMP - a3.COMP);                               \
            float d2 = fabsf(a2.COMP - a4.COMP);                               \
            const float* w = &sW[(c4 * 4 + CC) * 5 * 8];                       \
            for (int o = 0; o < 8; o++)                                       \
                acc[o] += g0 * w[o] + s1 * w[8 + o] + s2 * w[16 + o]           \
                        + d1 * w[24 + o] + d2 * w[32 + o];                     \
        }
        PROC(x, 0) PROC(y, 1) PROC(z, 2) PROC(w, 3)
#undef PROC
    }
    float* po = out + ((size_t)bb * E + e) * 8;
    *reinterpret_cast<float4*>(po)     = make_float4(acc[0], acc[1], acc[2], acc[3]);
    *reinterpret_cast<float4*>(po + 4) = make_float4(acc[4], acc[5], acc[6], acc[7]);
}

// ---------------------------------------------------------------------------
// unpool + skip
// ---------------------------------------------------------------------------
template<int C>
__global__ __launch_bounds__(256) void unpool_skip(
    const float* __restrict__ up, const int* __restrict__ unpool,
    const float* __restrict__ skip, float* __restrict__ out,
    int Eout, int Ein)
{
    constexpr int TE = 32;
    __shared__ float ssk[C][TE + 1];
    __shared__ int su[TE];
    int tid = threadIdx.x;
    int bb = blockIdx.y;
    int e0 = blockIdx.x * TE;
    if (tid < TE) su[tid] = unpool[e0 + tid];
    const float* skb = skip + (size_t)bb * C * Eout;
    for (int i = tid; i < C * TE; i += 256) {
        int c = i >> 5, e = i & 31;
        ssk[c][e] = skb[(size_t)c * Eout + e0 + e];
    }
    __syncthreads();
    const float* upb = up + (size_t)bb * Ein * C;
    float* ob = out + ((size_t)bb * Eout + e0) * C;
    for (int i = tid; i < C * TE; i += 256) {
        int el = i / C, c = i % C;
        ob[(size_t)el * C + c] = upb[(size_t)su[el] * C + c] + ssk[c][el];
    }
}

// ---------------------------------------------------------------------------
// Instance norm
// ---------------------------------------------------------------------------
template<int C, int CHUNK>
__global__ __launch_bounds__(256) void inorm_partial(
    const float* __restrict__ x, int E, double* __restrict__ stats)
{
    constexpr int C4 = C / 4;
    constexpr int ESTEP = 256 / C4;
    __shared__ float rb[256][8];
    int tid = threadIdx.x;
    int c4 = tid % C4, er = tid / C4;
    int bb = blockIdx.z;
    int e0 = blockIdx.x * CHUNK;
    const float4* xb4 = reinterpret_cast<const float4*>(x + ((size_t)bb * E + e0) * C) + c4;
    float s0 = 0, s1 = 0, s2 = 0, s3 = 0, q0 = 0, q1 = 0, q2 = 0, q3 = 0;
    for (int e = er; e < CHUNK; e += ESTEP) {
        float4 v = xb4[(size_t)e * C4];
        s0 += v.x; q0 += v.x * v.x;
        s1 += v.y; q1 += v.y * v.y;
        s2 += v.z; q2 += v.z * v.z;
        s3 += v.w; q3 += v.w * v.w;
    }
    rb[tid][0] = s0; rb[tid][1] = s1; rb[tid][2] = s2; rb[tid][3] = s3;
    rb[tid][4] = q0; rb[tid][5] = q1; rb[tid][6] = q2; rb[tid][7] = q3;
    __syncthreads();
    for (int st = ESTEP / 2; st >= 1; st >>= 1) {
        if (er < st) {
#pragma unroll
            for (int u = 0; u < 8; u++) rb[tid][u] += rb[tid + st * C4][u];
        }
        __syncthreads();
    }
    if (er == 0) {
#pragma unroll
        for (int u = 0; u < 4; u++) {
            atomicAdd(&stats[((size_t)bb * C + c4 * 4 + u) * 2],     (double)rb[tid][u]);
            atomicAdd(&stats[((size_t)bb * C + c4 * 4 + u) * 2 + 1], (double)rb[tid][4 + u]);
        }
    }
}

__global__ void finalize_stats(const double* __restrict__ stats,
                               float2* __restrict__ mstat, int n, int E)
{
    int i = threadIdx.x;
    if (i >= n) return;
    double invE = 1.0 / (double)E;
    double m = stats[2 * i] * invE;
    double var = stats[2 * i + 1] * invE - m * m;
    mstat[i] = make_float2((float)m, rsqrtf((float)var + 1e-5f));
}

template<int C>
__global__ __launch_bounds__(256) void inorm_apply(
    float* __restrict__ x, int E, const float2* __restrict__ mstat)
{
    int idx = blockIdx.x * 256 + threadIdx.x;
    int c = idx % C;
    int bb = idx / (E * C);
    float2 mr = mstat[bb * C + c];
    float v = (x[idx] - mr.x) * mr.y;
    x[idx] = v > 0.f ? v : 0.f;
}

__global__ __launch_bounds__(256) void inorm_apply_final(
    const float* __restrict__ x, int E, const float2* __restrict__ mstat,
    float* __restrict__ out)
{
    __shared__ float sm[256];
    int tid = threadIdx.x;
    int bb = blockIdx.y;
    int e0 = blockIdx.x * 32;
    float2 mr = mstat[bb * 8 + (tid & 7)];
    float v = (x[((size_t)bb * E + e0) * 8 + tid] - mr.x) * mr.y;
    sm[tid] = v > 0.f ? v : 0.f;
    __syncthreads();
    int c = tid >> 5, el = tid & 31;
    out[((size_t)bb * 8 + c) * E + e0 + el] = sm[el * 8 + c];
}

// ---------------------------------------------------------------------------
// Host driver
// ---------------------------------------------------------------------------
extern "C" void kernel_launch(void* const* d_in, const int* in_sizes, int n_in,
                              void* d_out, int out_size)
{
    (void)in_sizes; (void)n_in; (void)out_size;
    const int E0 = 16384, E1 = 32768, E2 = 65536, E3 = 131072;

    const float* fe    = (const float*)d_in[0];
    const float* skip0 = (const float*)d_in[1];
    const float* skip1 = (const float*)d_in[2];
    const float* skip2 = (const float*)d_in[3];
    const int4*  gm0   = (const int4*)d_in[4];
    const int4*  gm1   = (const int4*)d_in[5];
    const int4*  gm2   = (const int4*)d_in[6];
    const int4*  gm3   = (const int4*)d_in[7];
    const int*   up0   = (const int*)d_in[8];
    const int*   up1   = (const int*)d_in[9];
    const int*   up2   = (const int*)d_in[10];
    const float* Wup0 = (const float*)d_in[11]; const float* bup0 = (const float*)d_in[12];
    const float* Wc0  = (const float*)d_in[13]; const float* bc0  = (const float*)d_in[14];
    const float* Wup1 = (const float*)d_in[15]; const float* bup1 = (const float*)d_in[16];
    const float* Wc1  = (const float*)d_in[17]; const float* bc1  = (const float*)d_in[18];
    const float* Wup2 = (const float*)d_in[19]; const float* bup2 = (const float*)d_in[20];
    const float* Wc2  = (const float*)d_in[21]; const float* bc2  = (const float*)d_in[22];
    const float* Wupf = (const float*)d_in[23]; const float* bupf = (const float*)d_in[24];
    const float* Wcf  = (const float*)d_in[25]; const float* bcf  = (const float*)d_in[26];
    float* outp = (float*)d_out;

    float *bufA, *bufB, *bufU, *bufY, *wt; double* stats; float2* mstat;
    __nv_bfloat16 *whi, *wlo;
    cudaGetSymbolAddress((void**)&bufA, g_bufA);
    cudaGetSymbolAddress((void**)&bufB, g_bufB);
    cudaGetSymbolAddress((void**)&bufU, g_bufU);
    cudaGetSymbolAddress((void**)&bufY, g_bufY);
    cudaGetSymbolAddress((void**)&wt,   g_wt);
    cudaGetSymbolAddress((void**)&whi,  g_whi);
    cudaGetSymbolAddress((void**)&wlo,  g_wlo);
    cudaGetSymbolAddress((void**)&stats, g_stats);
    cudaGetSymbolAddress((void**)&mstat, g_mstat);

    float* Wt_upf = wt + 322560;
    float* Wt_cf  = wt + 323840;

    __nv_bfloat16* Whi_up0 = whi;            __nv_bfloat16* Wlo_up0 = wlo;
    __nv_bfloat16* Whi_c0  = whi + 262144;   __nv_bfloat16* Wlo_c0  = wlo + 262144;
    __nv_bfloat16* Whi_up1 = whi + 393216;   __nv_bfloat16* Wlo_up1 = wlo + 393216;
    __nv_bfloat16* Whi_c1  = whi + 458752;   __nv_bfloat16* Wlo_c1  = wlo + 458752;
    __nv_bfloat16* Whi_up2 = whi + 491520;   __nv_bfloat16* Wlo_up2 = wlo + 491520;
    __nv_bfloat16* Whi_c2  = whi + 507904;   __nv_bfloat16* Wlo_c2  = wlo + 507904;

    double* stats0 = stats;
    double* stats1 = stats + 512;
    double* stats2 = stats + 768;
    double* statsF = stats + 896;
    float2* mst0 = mstat;
    float2* mst1 = mstat + 256;
    float2* mst2 = mstat + 384;
    float2* mstF = mstat + 448;

    // dynamic smem: 4 A tiles (18432 each) + idx
    const int SMEMT = 4 * 18432 + 2048;   // 75776
    cudaFuncSetAttribute(conv_t<256, 128>, cudaFuncAttributeMaxDynamicSharedMemorySize, SMEMT);
    cudaFuncSetAttribute(conv_t<128, 128>, cudaFuncAttributeMaxDynamicSharedMemorySize, SMEMT);
    cudaFuncSetAttribute(conv_t<128, 64>,  cudaFuncAttributeMaxDynamicSharedMemorySize, SMEMT);
    cudaFuncSetAttribute(conv_t<64, 64>,   cudaFuncAttributeMaxDynamicSharedMemorySize, SMEMT);
    cudaFuncSetAttribute(conv_t<64, 32>,   cudaFuncAttributeMaxDynamicSharedMemorySize, SMEMT);
    cudaFuncSetAttribute(conv_t<32, 32>,   cudaFuncAttributeMaxDynamicSharedMemorySize, SMEMT);

    // launches: wtrans+zero(0), wbf(1), xpose(2), conv_t up0(3 = ncu target)
    wtrans_all<<<1267, 256>>>(Wup0, Wc0, Wup1, Wc1, Wup2, Wc2, Wupf, Wcf, wt, stats);
    wbf_frag<<<2016, 256>>>(Wup0, Wc0, Wup1, Wc1, Wup2, Wc2, whi, wlo);
    xpose<<<dim3(E0 / 32, 256 / 32, 2), dim3(32, 8)>>>(fe, bufA, E0, 256);

    // ---- Level 0 ----
    conv_t<256, 128><<<dim3(E0 / 128, 2), 256, SMEMT>>>(bufA, gm0, Whi_up0, Wlo_up0, bup0, bufU, E0);
    unpool_skip<128><<<dim3(E1 / 32, 2), 256>>>(bufU, up0, skip0, bufY, E1, E0);
    conv_t<128, 128><<<dim3(E1 / 128, 2), 256, SMEMT>>>(bufY, gm1, Whi_c0, Wlo_c0, bc0, bufB, E1);
    inorm_partial<128, 256><<<dim3(E1 / 256, 1, 2), 256>>>(bufB, E1, stats0);
    finalize_stats<<<1, 256>>>(stats0, mst0, 256, E1);
    inorm_apply<128><<<(2 * E1 * 128) / 256, 256>>>(bufB, E1, mst0);

    // ---- Level 1 ----
    conv_t<128, 64><<<dim3(E1 / 128, 2), 256, SMEMT>>>(bufB, gm1, Whi_up1, Wlo_up1, bup1, bufU, E1);
    unpool_skip<64><<<dim3(E2 / 32, 2), 256>>>(bufU, up1, skip1, bufY, E2, E1);
    conv_t<64, 64><<<dim3(E2 / 128, 2), 256, SMEMT>>>(bufY, gm2, Whi_c1, Wlo_c1, bc1, bufA, E2);
    inorm_partial<64, 512><<<dim3(E2 / 512, 1, 2), 256>>>(bufA, E2, stats1);
    finalize_stats<<<1, 128>>>(stats1, mst1, 128, E2);
    inorm_apply<64><<<(2 * E2 * 64) / 256, 256>>>(bufA, E2, mst1);

    // ---- Level 2 ----
    conv_t<64, 32><<<dim3(E2 / 128, 2), 256, SMEMT>>>(bufA, gm2, Whi_up2, Wlo_up2, bup2, bufU, E2);
    unpool_skip<32><<<dim3(E3 / 32, 2), 256>>>(bufU, up2, skip2, bufY, E3, E2);
    conv_t<32, 32><<<dim3(E3 / 128, 2), 256, SMEMT>>>(bufY, gm3, Whi_c2, Wlo_c2, bc2, bufB, E3);
    inorm_partial<32, 1024><<<dim3(E3 / 1024, 1, 2), 256>>>(bufB, E3, stats2);
    finalize_stats<<<1, 64>>>(stats2, mst2, 64, E3);
    inorm_apply<32><<<(2 * E3 * 32) / 256, 256>>>(bufB, E3, mst2);

    // ---- Final ----
    conv_small<32><<<dim3(E3 / 256, 2), 256>>>(bufB, gm3, Wt_upf, bupf, bufU, E3);
    conv_small<8><<<dim3(E3 / 256, 2), 256>>>(bufU, gm3, Wt_cf, bcf, bufY, E3);
    inorm_partial<8, 4096><<<dim3(E3 / 4096, 1, 2), 256>>>(bufY, E3, statsF);
    finalize_stats<<<1, 16>>>(statsF, mstF, 16, E3);
    inorm_apply_final<<<dim3(E3 / 32, 2), 256>>>(bufY, E3, mstF, outp);
}

// round 10
// speedup vs baseline: 2.0296x; 1.1733x over previous
#include <cuda_runtime.h>
#include <cuda_bf16.h>
#include <math.h>
#include <stdint.h>

// ---------------------------------------------------------------------------
// Static device scratch. Activations in (B, E, C) layout: x[(b*E+e)*C + c].
// ---------------------------------------------------------------------------
__device__ float  g_bufA[8388608];
__device__ float  g_bufB[8388608];
__device__ float  g_bufU[4194304];
__device__ float  g_bufY[8388608];
__device__ float  g_wt[400000];      // transposed fp32 weights (conv_small)
__device__ __align__(16) __nv_bfloat16 g_wb[774144];   // fragment-ordered, interleaved {hi0,hi1,lo0,lo1}
__device__ double g_stats[1024];
__device__ float2 g_mstat[512];

__device__ __forceinline__ uint32_t smem_u32(const void* p) {
    uint32_t a;
    asm("{ .reg .u64 t; cvta.to.shared.u64 t, %1; cvt.u32.u64 %0, t; }" : "=r"(a) : "l"(p));
    return a;
}

#define STS16(a, v) \
    asm volatile("st.shared.b16 [%0], %1;" :: "r"(a), "h"(v) : "memory")

#define STS128Z(a) \
    asm volatile("st.shared.v4.b32 [%0], {%1, %1, %1, %1};" :: "r"(a), "r"(0u) : "memory")

#define LDMX4(r, addr) \
    asm volatile("ldmatrix.sync.aligned.m8n8.x4.shared.b16 {%0,%1,%2,%3}, [%4];" \
        : "=r"((r)[0]), "=r"((r)[1]), "=r"((r)[2]), "=r"((r)[3]) : "r"(addr))

#define MMA16816(d, a, b0, b1) \
    asm volatile("mma.sync.aligned.m16n8k16.row.col.f32.bf16.bf16.f32 " \
        "{%0,%1,%2,%3}, {%4,%5,%6,%7}, {%8,%9}, {%0,%1,%2,%3};" \
        : "+f"((d)[0]), "+f"((d)[1]), "+f"((d)[2]), "+f"((d)[3]) \
        : "r"((a)[0]), "r"((a)[1]), "r"((a)[2]), "r"((a)[3]), "r"(b0), "r"(b1))

__device__ __forceinline__ unsigned short bfbits(__nv_bfloat16 h) {
    return *reinterpret_cast<unsigned short*>(&h);
}

// ---------------------------------------------------------------------------
// fp32 weight transpose (conv_small path) + stats zeroing (fused)
// ---------------------------------------------------------------------------
__global__ void wtrans_all(const float* __restrict__ W0, const float* __restrict__ W1,
                           const float* __restrict__ W2, const float* __restrict__ W3,
                           const float* __restrict__ W4, const float* __restrict__ W5,
                           const float* __restrict__ W6, const float* __restrict__ W7,
                           float* __restrict__ wt, double* __restrict__ stats)
{
    int i = blockIdx.x * 256 + threadIdx.x;
    if (i < 1024) stats[i] = 0.0;
    if (i >= 324160) return;
    const int Ks[8]   = {1280, 640, 640, 320, 320, 160, 160, 40};
    const int Cs[8]   = {128, 128, 64, 64, 32, 32, 8, 8};
    const int offs[9] = {0, 163840, 245760, 286720, 307200, 317440, 322560, 323840, 324160};
    const float* Ws[8] = {W0, W1, W2, W3, W4, W5, W6, W7};
    int seg = 0;
    while (i >= offs[seg + 1]) seg++;
    int j = i - offs[seg];
    int K = Ks[seg], C = Cs[seg];
    int k = j / C, o = j % C;
    wt[i] = Ws[seg][(size_t)o * K + k];
}

// ---------------------------------------------------------------------------
// Fragment-ordered bf16 weights, 48-k chunks (40 real + 8 pad), hi/lo
// interleaved per uint4: {hi_reg0, hi_reg1, lo_reg0, lo_reg1}.
// uint4 index = ((chunk*(COUT/8) + naG)*3 + ka)*32 + lane.
// kk = ka*16 + (lane%4)*2 + half + rr*8;  kk<40: s=kk>>3, cc=kk&7, c=chunk*8+cc.
// ---------------------------------------------------------------------------
__global__ void wbf48(const float* __restrict__ W0, const float* __restrict__ W1,
                      const float* __restrict__ W2, const float* __restrict__ W3,
                      const float* __restrict__ W4, const float* __restrict__ W5,
                      __nv_bfloat16* __restrict__ wb)
{
    int i = blockIdx.x * 256 + threadIdx.x;
    if (i >= 774144) return;
    const int CINs[6]  = {256, 128, 128, 64, 64, 32};
    const int COUTs[6] = {128, 128, 64, 64, 32, 32};
    const int offs[7]  = {0, 393216, 589824, 688128, 737280, 761856, 774144};
    const float* Ws[6] = {W0, W1, W2, W3, W4, W5};
    int seg = 0;
    while (i >= offs[seg + 1]) seg++;
    int j = i - offs[seg];
    int CIN = CINs[seg], COUT = COUTs[seg];
    int half = j & 1;
    int reg  = (j >> 1) & 3;
    int lane = (j >> 3) & 31;
    int t    = j >> 8;
    int ka   = t % 3;  t /= 3;
    int naG  = t % (COUT / 8);
    int chunk = t / (COUT / 8);
    int rr = reg & 1;
    bool lo = (reg >= 2);
    int n  = naG * 8 + (lane >> 2);
    int kk = ka * 16 + (lane & 3) * 2 + half + rr * 8;
    float v = 0.f;
    if (kk < 40) {
        int s = kk >> 3, cc = kk & 7;
        int c = chunk * 8 + cc;
        v = Ws[seg][(size_t)n * (CIN * 5) + c * 5 + s];
    }
    __nv_bfloat16 h = __float2bfloat16(v);
    wb[i] = lo ? __float2bfloat16(v - __bfloat162float(h)) : h;
}

// ---------------------------------------------------------------------------
// fe (B, C, E) -> (B, E, C) tiled transpose
// ---------------------------------------------------------------------------
__global__ void xpose(const float* __restrict__ in, float* __restrict__ outT,
                      int E, int C) {
    __shared__ float tile[32][33];
    int bb = blockIdx.z;
    int e0 = blockIdx.x * 32, c0 = blockIdx.y * 32;
    int tx = threadIdx.x, ty = threadIdx.y;          // (32, 8)
    const float* inb = in + (size_t)bb * C * E;
    float* ob = outT + (size_t)bb * E * C;
#pragma unroll
    for (int j = 0; j < 32; j += 8)
        tile[ty + j][tx] = inb[(size_t)(c0 + ty + j) * E + e0 + tx];
    __syncthreads();
#pragma unroll
    for (int j = 0; j < 32; j += 8)
        ob[(size_t)(e0 + ty + j) * C + c0 + tx] = tile[tx][ty + j];
}

// ---------------------------------------------------------------------------
// Tensor-core mesh conv (m16n8k16 bf16 mma.sync), 48-k chunks, double-buffered
// A tiles + register-prefetched gathers. Optional fused inorm+relu on input.
// Padding k-columns [40,48) of all A buffers zeroed ONCE before the loop
// (never rewritten) so padded MMAs multiply exact zeros, not garbage.
// ---------------------------------------------------------------------------
template<int CIN, int COUT, bool NORM>
__global__ __launch_bounds__(256, 2) void conv_t(
    const float* __restrict__ x, const int4* __restrict__ gemm,
    const __nv_bfloat16* __restrict__ Wb, const float2* __restrict__ mstat,
    const float* __restrict__ bias, float* __restrict__ out, int E)
{
    constexpr int CHUNKS = CIN / 8;
    constexpr int NA = COUT / 16;
    constexpr int PITCH = 112;          // 48 bf16 = 96B + 16B pad; conflict-free
    constexpr int ABUF = 128 * PITCH;   // 14336 B

    extern __shared__ char smem_raw[];
    const uint32_t sAU = smem_u32(smem_raw);     // 4 tiles: [buf][hi/lo]
    int4* sIdx = reinterpret_cast<int4*>(smem_raw + 4 * ABUF);

    const int tid = threadIdx.x;
    const int wid = tid >> 5, lane = tid & 31;
    const int wm = wid & 3, wn = wid >> 2;
    const int bb = blockIdx.y;
    const int e0 = blockIdx.x * 128;
    const float* xb = x + (size_t)bb * E * CIN;

    for (int i = tid; i < 128; i += 256) sIdx[i] = gemm[e0 + i];
    // zero the padding k-columns (bytes [80,96) of each row) of all 4 buffers
    for (int i = tid; i < 4 * 128; i += 256)
        STS128Z(sAU + (uint32_t)(i >> 7) * ABUF + (uint32_t)(i & 127) * PITCH + 80);

    const int cc = tid & 7;        // channel-in-chunk
    const int elb = tid >> 3;      // edge base (0..31), items at elb+32q

    float acc[2][NA][4];
#pragma unroll
    for (int ma = 0; ma < 2; ma++)
#pragma unroll
        for (int na = 0; na < NA; na++)
#pragma unroll
            for (int u = 0; u < 4; u++) acc[ma][na][u] = 0.f;

    const uint4* wb4 = reinterpret_cast<const uint4*>(Wb);

    __syncthreads();   // sIdx + padding ready

    float g[4][5];
    auto gather = [&](int chunk) {
        const float* xc = xb + chunk * 8 + cc;
        float2 mr = make_float2(0.f, 1.f);
        if constexpr (NORM) mr = mstat[bb * CIN + chunk * 8 + cc];
#pragma unroll
        for (int q = 0; q < 4; q++) {
            int el = elb + 32 * q;
            int4 n = sIdx[el];
            float xe = xc[(size_t)(e0 + el) * CIN];
            float f1 = xc[(size_t)n.x * CIN];
            float f2 = xc[(size_t)n.y * CIN];
            float f3 = xc[(size_t)n.z * CIN];
            float f4 = xc[(size_t)n.w * CIN];
            if constexpr (NORM) {
                xe = fmaxf((xe - mr.x) * mr.y, 0.f);
                f1 = fmaxf((f1 - mr.x) * mr.y, 0.f);
                f2 = fmaxf((f2 - mr.x) * mr.y, 0.f);
                f3 = fmaxf((f3 - mr.x) * mr.y, 0.f);
                f4 = fmaxf((f4 - mr.x) * mr.y, 0.f);
            }
            g[q][0] = xe;
            g[q][1] = f1 + f3;  g[q][2] = f2 + f4;
            g[q][3] = fabsf(f1 - f3);  g[q][4] = fabsf(f2 - f4);
        }
    };

    gather(0);

    for (int chunk = 0; chunk < CHUNKS; chunk++) {
        const uint32_t bufHi = sAU + (uint32_t)((chunk & 1) * 2) * ABUF;
        const uint32_t bufLo = bufHi + ABUF;
        // ---- commit prefetched gathers: value (cc,s) at byte s*16 + cc*2 ----
#pragma unroll
        for (int q = 0; q < 4; q++) {
            int el = elb + 32 * q;
            uint32_t base = (uint32_t)el * PITCH + (uint32_t)cc * 2;
#pragma unroll
            for (int s = 0; s < 5; s++) {
                __nv_bfloat16 h = __float2bfloat16(g[q][s]);
                STS16(bufHi + base + s * 16, bfbits(h));
                STS16(bufLo + base + s * 16,
                      bfbits(__float2bfloat16(g[q][s] - __bfloat162float(h))));
            }
        }
        __syncthreads();
        // ---- prefetch next chunk's gathers (latency hidden by mma below) ----
        if (chunk + 1 < CHUNKS) gather(chunk + 1);
        // ---- ldmatrix + mma ----
#pragma unroll
        for (int ka = 0; ka < 3; ka++) {
            uint32_t ah[2][4], al[2][4];
#pragma unroll
            for (int ma = 0; ma < 2; ma++) {
                uint32_t off = (uint32_t)(wm * 32 + ma * 16 + (lane & 15)) * PITCH
                             + (uint32_t)ka * 32 + ((lane >> 4) * 16);
                LDMX4(ah[ma], bufHi + off);
                LDMX4(al[ma], bufLo + off);
            }
#pragma unroll
            for (int na = 0; na < NA; na++) {
                uint4 wv = wb4[(size_t)(((chunk * (COUT / 8) + wn * NA + na) * 3 + ka) * 32 + lane)];
#pragma unroll
                for (int ma = 0; ma < 2; ma++) {
                    MMA16816(acc[ma][na], ah[ma], wv.x, wv.y);
                    MMA16816(acc[ma][na], al[ma], wv.x, wv.y);
                    MMA16816(acc[ma][na], ah[ma], wv.z, wv.w);
                }
            }
        }
    }

    // ---- epilogue: acc + bias -> out ----
    const int rbase = e0 + wm * 32 + (lane >> 2);
#pragma unroll
    for (int ma = 0; ma < 2; ma++) {
#pragma unroll
        for (int na = 0; na < NA; na++) {
            int col = wn * NA * 8 + na * 8 + (lane & 3) * 2;
            float bx = bias[col], by = bias[col + 1];
            int row0 = rbase + ma * 16;
            float* p0 = out + ((size_t)bb * E + row0) * COUT + col;
            float* p1 = p0 + (size_t)8 * COUT;
            *reinterpret_cast<float2*>(p0) =
                make_float2(acc[ma][na][0] + bx, acc[ma][na][1] + by);
            *reinterpret_cast<float2*>(p1) =
                make_float2(acc[ma][na][2] + bx, acc[ma][na][3] + by);
        }
    }
}

// ---------------------------------------------------------------------------
// Small-Cout mesh-conv (COUT = 8), fp32, optional fused inorm+relu on input
// ---------------------------------------------------------------------------
template<int CIN, bool NORM>
__global__ __launch_bounds__(256) void conv_small(
    const float* __restrict__ x, const int4* __restrict__ gemm,
    const float* __restrict__ Wt, const float2* __restrict__ mstat,
    const float* __restrict__ bias, float* __restrict__ out, int E)
{
    constexpr int K = CIN * 5;
    __shared__ float sW[K * 8];
    __shared__ float2 sM[CIN];
    int tid = threadIdx.x;
    int bb = blockIdx.y;
    for (int i = tid; i < K * 8; i += 256) sW[i] = Wt[i];
    if (NORM && tid < CIN) sM[tid] = mstat[bb * CIN + tid];
    float acc[8];
#pragma unroll
    for (int o = 0; o < 8; o++) acc[o] = bias[o];
    __syncthreads();

    int e = blockIdx.x * 256 + tid;
    int4 n = gemm[e];
    const float* xb = x + (size_t)bb * E * CIN;
    const float4* r0 = reinterpret_cast<const float4*>(xb + (size_t)e * CIN);
    const float4* r1 = reinterpret_cast<const float4*>(xb + (size_t)n.x * CIN);
    const float4* r2 = reinterpret_cast<const float4*>(xb + (size_t)n.y * CIN);
    const float4* r3 = reinterpret_cast<const float4*>(xb + (size_t)n.z * CIN);
    const float4* r4 = reinterpret_cast<const float4*>(xb + (size_t)n.w * CIN);

#pragma unroll 2
    for (int c4 = 0; c4 < CIN / 4; c4++) {
        float4 xe = r0[c4], a1 = r1[c4], a2 = r2[c4], a3 = r3[c4], a4 = r4[c4];
#define PROC(COMP, CC)                                                         \
        {                                                                      \
            float xv = xe.COMP, v1 = a1.COMP, v2 = a2.COMP,                    \
                  v3 = a3.COMP, v4 = a4.COMP;                                  \
            if constexpr (NORM) {                                              \
                float2 mm = sM[c4 * 4 + CC];                                   \
                xv = fmaxf((xv - mm.x) * mm.y, 0.f);                           \
                v1 = fmaxf((v1 - mm.x) * mm.y, 0.f);                           \
                v2 = fmaxf((v2 - mm.x) * mm.y, 0.f);                           \
                v3 = fmaxf((v3 - mm.x) * mm.y, 0.f);                           \
                v4 = fmaxf((v4 - mm.x) * mm.y, 0.f);                           \
            }                                                                  \
            float g0 = xv;                                                     \
            float s1 = v1 + v3;                                                \
            float s2 = v2 + v4;                                                \
            float d1 = fabsf(v1 - v3);                                         \
            float d2 = fabsf(v2 - v4);                                         \
            const float* w = &sW[(c4 * 4 + CC) * 5 * 8];                       \
            for (int o = 0; o < 8; o++)                                        \
                acc[o] += g0 * w[o] + s1 * w[8 + o] + s2 * w[16 + o]           \
                        + d1 * w[24 + o] + d2 * w[32 + o];                     \
        }
        PROC(x, 0) PROC(y, 1) PROC(z, 2) PROC(w, 3)
#undef PROC
    }
    float* po = out + ((size_t)bb * E + e) * 8;
    *reinterpret_cast<float4*>(po)     = make_float4(acc[0], acc[1], acc[2], acc[3]);
    *reinterpret_cast<float4*>(po + 4) = make_float4(acc[4], acc[5], acc[6], acc[7]);
}

// ---------------------------------------------------------------------------
// unpool + skip
// ---------------------------------------------------------------------------
template<int C>
__global__ __launch_bounds__(256) void unpool_skip(
    const float* __restrict__ up, const int* __restrict__ unpool,
    const float* __restrict__ skip, float* __restrict__ out,
    int Eout, int Ein)
{
    constexpr int TE = 32;
    __shared__ float ssk[C][TE + 1];
    __shared__ int su[TE];
    int tid = threadIdx.x;
    int bb = blockIdx.y;
    int e0 = blockIdx.x * TE;
    if (tid < TE) su[tid] = unpool[e0 + tid];
    const float* skb = skip + (size_t)bb * C * Eout;
    for (int i = tid; i < C * TE; i += 256) {
        int c = i >> 5, e = i & 31;
        ssk[c][e] = skb[(size_t)c * Eout + e0 + e];
    }
    __syncthreads();
    const float* upb = up + (size_t)bb * Ein * C;
    float* ob = out + ((size_t)bb * Eout + e0) * C;
    for (int i = tid; i < C * TE; i += 256) {
        int el = i / C, c = i % C;
        ob[(size_t)el * C + c] = upb[(size_t)su[el] * C + c] + ssk[c][el];
    }
}

// ---------------------------------------------------------------------------
// Instance norm: partial stats + finalize
// ---------------------------------------------------------------------------
template<int C, int CHUNK>
__global__ __launch_bounds__(256) void inorm_partial(
    const float* __restrict__ x, int E, double* __restrict__ stats)
{
    constexpr int C4 = C / 4;
    constexpr int ESTEP = 256 / C4;
    __shared__ float rb[256][8];
    int tid = threadIdx.x;
    int c4 = tid % C4, er = tid / C4;
    int bb = blockIdx.z;
    int e0 = blockIdx.x * CHUNK;
    const float4* xb4 = reinterpret_cast<const float4*>(x + ((size_t)bb * E + e0) * C) + c4;
    float s0 = 0, s1 = 0, s2 = 0, s3 = 0, q0 = 0, q1 = 0, q2 = 0, q3 = 0;
    for (int e = er; e < CHUNK; e += ESTEP) {
        float4 v = xb4[(size_t)e * C4];
        s0 += v.x; q0 += v.x * v.x;
        s1 += v.y; q1 += v.y * v.y;
        s2 += v.z; q2 += v.z * v.z;
        s3 += v.w; q3 += v.w * v.w;
    }
    rb[tid][0] = s0; rb[tid][1] = s1; rb[tid][2] = s2; rb[tid][3] = s3;
    rb[tid][4] = q0; rb[tid][5] = q1; rb[tid][6] = q2; rb[tid][7] = q3;
    __syncthreads();
    for (int st = ESTEP / 2; st >= 1; st >>= 1) {
        if (er < st) {
#pragma unroll
            for (int u = 0; u < 8; u++) rb[tid][u] += rb[tid + st * C4][u];
        }
        __syncthreads();
    }
    if (er == 0) {
#pragma unroll
        for (int u = 0; u < 4; u++) {
            atomicAdd(&stats[((size_t)bb * C + c4 * 4 + u) * 2],     (double)rb[tid][u]);
            atomicAdd(&stats[((size_t)bb * C + c4 * 4 + u) * 2 + 1], (double)rb[tid][4 + u]);
        }
    }
}

__global__ void finalize_stats(const double* __restrict__ stats,
                               float2* __restrict__ mstat, int n, int E)
{
    int i = threadIdx.x;
    if (i >= n) return;
    double invE = 1.0 / (double)E;
    double m = stats[2 * i] * invE;
    double var = stats[2 * i + 1] * invE - m * m;
    mstat[i] = make_float2((float)m, rsqrtf((float)var + 1e-5f));
}

// Final: reads (B,E,8), writes d_out (B,8,E) with norm+relu, smem transpose.
__global__ __launch_bounds__(256) void inorm_apply_final(
    const float* __restrict__ x, int E, const float2* __restrict__ mstat,
    float* __restrict__ out)
{
    __shared__ float sm[256];
    int tid = threadIdx.x;
    int bb = blockIdx.y;
    int e0 = blockIdx.x * 32;
    float2 mr = mstat[bb * 8 + (tid & 7)];
    float v = (x[((size_t)bb * E + e0) * 8 + tid] - mr.x) * mr.y;
    sm[tid] = v > 0.f ? v : 0.f;
    __syncthreads();
    int c = tid >> 5, el = tid & 31;
    out[((size_t)bb * 8 + c) * E + e0 + el] = sm[el * 8 + c];
}

// ---------------------------------------------------------------------------
// Host driver
// ---------------------------------------------------------------------------
extern "C" void kernel_launch(void* const* d_in, const int* in_sizes, int n_in,
                              void* d_out, int out_size)
{
    (void)in_sizes; (void)n_in; (void)out_size;
    const int E0 = 16384, E1 = 32768, E2 = 65536, E3 = 131072;

    const float* fe    = (const float*)d_in[0];
    const float* skip0 = (const float*)d_in[1];
    const float* skip1 = (const float*)d_in[2];
    const float* skip2 = (const float*)d_in[3];
    const int4*  gm0   = (const int4*)d_in[4];
    const int4*  gm1   = (const int4*)d_in[5];
    const int4*  gm2   = (const int4*)d_in[6];
    const int4*  gm3   = (const int4*)d_in[7];
    const int*   up0   = (const int*)d_in[8];
    const int*   up1   = (const int*)d_in[9];
    const int*   up2   = (const int*)d_in[10];
    const float* Wup0 = (const float*)d_in[11]; const float* bup0 = (const float*)d_in[12];
    const float* Wc0  = (const float*)d_in[13]; const float* bc0  = (const float*)d_in[14];
    const float* Wup1 = (const float*)d_in[15]; const float* bup1 = (const float*)d_in[16];
    const float* Wc1  = (const float*)d_in[17]; const float* bc1  = (const float*)d_in[18];
    const float* Wup2 = (const float*)d_in[19]; const float* bup2 = (const float*)d_in[20];
    const float* Wc2  = (const float*)d_in[21]; const float* bc2  = (const float*)d_in[22];
    const float* Wupf = (const float*)d_in[23]; const float* bupf = (const float*)d_in[24];
    const float* Wcf  = (const float*)d_in[25]; const float* bcf  = (const float*)d_in[26];
    float* outp = (float*)d_out;

    float *bufA, *bufB, *bufU, *bufY, *wt; double* stats; float2* mstat;
    __nv_bfloat16 *wb;
    cudaGetSymbolAddress((void**)&bufA, g_bufA);
    cudaGetSymbolAddress((void**)&bufB, g_bufB);
    cudaGetSymbolAddress((void**)&bufU, g_bufU);
    cudaGetSymbolAddress((void**)&bufY, g_bufY);
    cudaGetSymbolAddress((void**)&wt,   g_wt);
    cudaGetSymbolAddress((void**)&wb,   g_wb);
    cudaGetSymbolAddress((void**)&stats, g_stats);
    cudaGetSymbolAddress((void**)&mstat, g_mstat);

    float* Wt_upf = wt + 322560;
    float* Wt_cf  = wt + 323840;

    // wb offsets (bf16 units)
    __nv_bfloat16* Wb_up0 = wb;
    __nv_bfloat16* Wb_c0  = wb + 393216;
    __nv_bfloat16* Wb_up1 = wb + 589824;
    __nv_bfloat16* Wb_c1  = wb + 688128;
    __nv_bfloat16* Wb_up2 = wb + 737280;
    __nv_bfloat16* Wb_c2  = wb + 761856;

    double* stats0 = stats;
    double* stats1 = stats + 512;
    double* stats2 = stats + 768;
    double* statsF = stats + 896;
    float2* mst0 = mstat;
    float2* mst1 = mstat + 256;
    float2* mst2 = mstat + 384;
    float2* mstF = mstat + 448;

    // dynamic smem: 4 A tiles (14336 each) + idx
    const int SMEMT = 4 * 14336 + 2048;   // 59392
    cudaFuncSetAttribute(conv_t<256, 128, false>, cudaFuncAttributeMaxDynamicSharedMemorySize, SMEMT);
    cudaFuncSetAttribute(conv_t<128, 128, false>, cudaFuncAttributeMaxDynamicSharedMemorySize, SMEMT);
    cudaFuncSetAttribute(conv_t<128, 64, true>,   cudaFuncAttributeMaxDynamicSharedMemorySize, SMEMT);
    cudaFuncSetAttribute(conv_t<64, 64, false>,   cudaFuncAttributeMaxDynamicSharedMemorySize, SMEMT);
    cudaFuncSetAttribute(conv_t<64, 32, true>,    cudaFuncAttributeMaxDynamicSharedMemorySize, SMEMT);
    cudaFuncSetAttribute(conv_t<32, 32, false>,   cudaFuncAttributeMaxDynamicSharedMemorySize, SMEMT);

    // launches: wtrans+zero(0), wbf48(1), xpose(2), conv_t up0(3 = ncu target)
    wtrans_all<<<1267, 256>>>(Wup0, Wc0, Wup1, Wc1, Wup2, Wc2, Wupf, Wcf, wt, stats);
    wbf48<<<3024, 256>>>(Wup0, Wc0, Wup1, Wc1, Wup2, Wc2, wb);
    xpose<<<dim3(E0 / 32, 256 / 32, 2), dim3(32, 8)>>>(fe, bufA, E0, 256);

    // ---- Level 0 ----
    conv_t<256, 128, false><<<dim3(E0 / 128, 2), 256, SMEMT>>>(bufA, gm0, Wb_up0, nullptr, bup0, bufU, E0);
    unpool_skip<128><<<dim3(E1 / 32, 2), 256>>>(bufU, up0, skip0, bufY, E1, E0);
    conv_t<128, 128, false><<<dim3(E1 / 128, 2), 256, SMEMT>>>(bufY, gm1, Wb_c0, nullptr, bc0, bufB, E1);
    inorm_partial<128, 256><<<dim3(E1 / 256, 1, 2), 256>>>(bufB, E1, stats0);
    finalize_stats<<<1, 256>>>(stats0, mst0, 256, E1);

    // ---- Level 1 ---- (up1 consumes bufB with fused norm+relu)
    conv_t<128, 64, true><<<dim3(E1 / 128, 2), 256, SMEMT>>>(bufB, gm1, Wb_up1, mst0, bup1, bufU, E1);
    unpool_skip<64><<<dim3(E2 / 32, 2), 256>>>(bufU, up1, skip1, bufY, E2, E1);
    conv_t<64, 64, false><<<dim3(E2 / 128, 2), 256, SMEMT>>>(bufY, gm2, Wb_c1, nullptr, bc1, bufA, E2);
    inorm_partial<64, 512><<<dim3(E2 / 512, 1, 2), 256>>>(bufA, E2, stats1);
    finalize_stats<<<1, 128>>>(stats1, mst1, 128, E2);

    // ---- Level 2 ---- (up2 consumes bufA with fused norm+relu)
    conv_t<64, 32, true><<<dim3(E2 / 128, 2), 256, SMEMT>>>(bufA, gm2, Wb_up2, mst1, bup2, bufU, E2);
    unpool_skip<32><<<dim3(E3 / 32, 2), 256>>>(bufU, up2, skip2, bufY, E3, E2);
    conv_t<32, 32, false><<<dim3(E3 / 128, 2), 256, SMEMT>>>(bufY, gm3, Wb_c2, nullptr, bc2, bufB, E3);
    inorm_partial<32, 1024><<<dim3(E3 / 1024, 1, 2), 256>>>(bufB, E3, stats2);
    finalize_stats<<<1, 64>>>(stats2, mst2, 64, E3);

    // ---- Final ---- (upf consumes bufB with fused norm+relu)
    conv_small<32, true><<<dim3(E3 / 256, 2), 256>>>(bufB, gm3, Wt_upf, mst2, bupf, bufU, E3);
    conv_small<8, false><<<dim3(E3 / 256, 2), 256>>>(bufU, gm3, Wt_cf, nullptr, bcf, bufY, E3);
    inorm_partial<8, 4096><<<dim3(E3 / 4096, 1, 2), 256>>>(bufY, E3, statsF);
    finalize_stats<<<1, 16>>>(statsF, mstF, 16, E3);
    inorm_apply_final<<<dim3(E3 / 32, 2), 256>>>(bufY, E3, mstF, outp);
}

// round 12
// speedup vs baseline: 2.1734x; 1.0709x over previous
#include <cuda_runtime.h>
#include <cuda_bf16.h>
#include <math.h>
#include <stdint.h>

// ---------------------------------------------------------------------------
// Static device scratch. Activations in (B, E, C) layout: x[(b*E+e)*C + c].
// ---------------------------------------------------------------------------
__device__ float  g_bufA[8388608];
__device__ float  g_bufB[8388608];
__device__ float  g_bufU[4194304];
__device__ float  g_bufY[8388608];
__device__ float  g_wt[400000];      // transposed fp32 weights (conv_small)
__device__ __align__(16) __nv_bfloat16 g_wb[774144];   // fragment-ordered, interleaved {hi0,hi1,lo0,lo1}
__device__ double g_stats[1024];
__device__ float2 g_mstat[512];

__device__ __forceinline__ uint32_t smem_u32(const void* p) {
    uint32_t a;
    asm("{ .reg .u64 t; cvta.to.shared.u64 t, %1; cvt.u32.u64 %0, t; }" : "=r"(a) : "l"(p));
    return a;
}

#define STS16(a, v) \
    asm volatile("st.shared.b16 [%0], %1;" :: "r"(a), "h"(v) : "memory")

#define STS128Z(a) \
    asm volatile("st.shared.v4.b32 [%0], {%1, %1, %1, %1};" :: "r"(a), "r"(0u) : "memory")

#define LDMX4(r, addr) \
    asm volatile("ldmatrix.sync.aligned.m8n8.x4.shared.b16 {%0,%1,%2,%3}, [%4];" \
        : "=r"((r)[0]), "=r"((r)[1]), "=r"((r)[2]), "=r"((r)[3]) : "r"(addr))

#define LDS128(r0, r1, r2, r3, addr) \
    asm volatile("ld.shared.v4.b32 {%0,%1,%2,%3}, [%4];" \
        : "=r"(r0), "=r"(r1), "=r"(r2), "=r"(r3) : "r"(addr))

#define CPASYNC16(saddr, gptr) \
    asm volatile("cp.async.cg.shared.global [%0], [%1], 16;" \
        :: "r"(saddr), "l"(gptr) : "memory")

#define CPCOMMIT() asm volatile("cp.async.commit_group;" ::: "memory")
#define CPWAIT0()  asm volatile("cp.async.wait_group 0;" ::: "memory")

#define MMA16816(d, a, b0, b1) \
    asm volatile("mma.sync.aligned.m16n8k16.row.col.f32.bf16.bf16.f32 " \
        "{%0,%1,%2,%3}, {%4,%5,%6,%7}, {%8,%9}, {%0,%1,%2,%3};" \
        : "+f"((d)[0]), "+f"((d)[1]), "+f"((d)[2]), "+f"((d)[3]) \
        : "r"((a)[0]), "r"((a)[1]), "r"((a)[2]), "r"((a)[3]), "r"(b0), "r"(b1))

__device__ __forceinline__ unsigned short bfbits(__nv_bfloat16 h) {
    return *reinterpret_cast<unsigned short*>(&h);
}

// ---------------------------------------------------------------------------
// fp32 weight transpose (conv_small path) + stats zeroing (fused)
// ---------------------------------------------------------------------------
__global__ void wtrans_all(const float* __restrict__ W0, const float* __restrict__ W1,
                           const float* __restrict__ W2, const float* __restrict__ W3,
                           const float* __restrict__ W4, const float* __restrict__ W5,
                           const float* __restrict__ W6, const float* __restrict__ W7,
                           float* __restrict__ wt, double* __restrict__ stats)
{
    int i = blockIdx.x * 256 + threadIdx.x;
    if (i < 1024) stats[i] = 0.0;
    if (i >= 324160) return;
    const int Ks[8]   = {1280, 640, 640, 320, 320, 160, 160, 40};
    const int Cs[8]   = {128, 128, 64, 64, 32, 32, 8, 8};
    const int offs[9] = {0, 163840, 245760, 286720, 307200, 317440, 322560, 323840, 324160};
    const float* Ws[8] = {W0, W1, W2, W3, W4, W5, W6, W7};
    int seg = 0;
    while (i >= offs[seg + 1]) seg++;
    int j = i - offs[seg];
    int K = Ks[seg], C = Cs[seg];
    int k = j / C, o = j % C;
    wt[i] = Ws[seg][(size_t)o * K + k];
}

// ---------------------------------------------------------------------------
// Fragment-ordered bf16 weights, 48-k chunks (40 real + 8 pad), hi/lo
// interleaved per uint4: {hi_reg0, hi_reg1, lo_reg0, lo_reg1}.
// uint4 index = ((chunk*(COUT/8) + naG)*3 + ka)*32 + lane.
// kk = ka*16 + (lane%4)*2 + half + rr*8;  kk<40: s=kk>>3, cc=kk&7, c=chunk*8+cc.
// ---------------------------------------------------------------------------
__global__ void wbf48(const float* __restrict__ W0, const float* __restrict__ W1,
                      const float* __restrict__ W2, const float* __restrict__ W3,
                      const float* __restrict__ W4, const float* __restrict__ W5,
                      __nv_bfloat16* __restrict__ wb)
{
    int i = blockIdx.x * 256 + threadIdx.x;
    if (i >= 774144) return;
    const int CINs[6]  = {256, 128, 128, 64, 64, 32};
    const int COUTs[6] = {128, 128, 64, 64, 32, 32};
    const int offs[7]  = {0, 393216, 589824, 688128, 737280, 761856, 774144};
    const float* Ws[6] = {W0, W1, W2, W3, W4, W5};
    int seg = 0;
    while (i >= offs[seg + 1]) seg++;
    int j = i - offs[seg];
    int CIN = CINs[seg], COUT = COUTs[seg];
    int half = j & 1;
    int reg  = (j >> 1) & 3;
    int lane = (j >> 3) & 31;
    int t    = j >> 8;
    int ka   = t % 3;  t /= 3;
    int naG  = t % (COUT / 8);
    int chunk = t / (COUT / 8);
    int rr = reg & 1;
    bool lo = (reg >= 2);
    int n  = naG * 8 + (lane >> 2);
    int kk = ka * 16 + (lane & 3) * 2 + half + rr * 8;
    float v = 0.f;
    if (kk < 40) {
        int s = kk >> 3, cc = kk & 7;
        int c = chunk * 8 + cc;
        v = Ws[seg][(size_t)n * (CIN * 5) + c * 5 + s];
    }
    __nv_bfloat16 h = __float2bfloat16(v);
    wb[i] = lo ? __float2bfloat16(v - __bfloat162float(h)) : h;
}

// ---------------------------------------------------------------------------
// fe (B, C, E) -> (B, E, C) tiled transpose
// ---------------------------------------------------------------------------
__global__ void xpose(const float* __restrict__ in, float* __restrict__ outT,
                      int E, int C) {
    __shared__ float tile[32][33];
    int bb = blockIdx.z;
    int e0 = blockIdx.x * 32, c0 = blockIdx.y * 32;
    int tx = threadIdx.x, ty = threadIdx.y;          // (32, 8)
    const float* inb = in + (size_t)bb * C * E;
    float* ob = outT + (size_t)bb * E * C;
#pragma unroll
    for (int j = 0; j < 32; j += 8)
        tile[ty + j][tx] = inb[(size_t)(c0 + ty + j) * E + e0 + tx];
    __syncthreads();
#pragma unroll
    for (int j = 0; j < 32; j += 8)
        ob[(size_t)(e0 + ty + j) * C + c0 + tx] = tile[tx][ty + j];
}

// ---------------------------------------------------------------------------
// Tensor-core mesh conv (m16n8k16 bf16 mma.sync), 48-k chunks.
// A tiles double-buffered + register-prefetched gathers.
// B tiles double-buffered via cp.async, staged AFTER the barrier (race-free:
// the barrier orders mma(chunk-1)'s reads of buf (chunk+1)&1 before the
// overwrite) and waited with wait_group 0 before the barrier of the
// consuming iteration.
// ---------------------------------------------------------------------------
template<int CIN, int COUT, bool NORM>
__global__ __launch_bounds__(256, 2) void conv_t(
    const float* __restrict__ x, const int4* __restrict__ gemm,
    const __nv_bfloat16* __restrict__ Wb, const float2* __restrict__ mstat,
    const float* __restrict__ bias, float* __restrict__ out, int E)
{
    constexpr int CHUNKS = CIN / 8;
    constexpr int NA = COUT / 16;
    constexpr int PITCH = 112;          // 48 bf16 = 96B + 16B pad; conflict-free
    constexpr int ABUF = 128 * PITCH;   // 14336 B
    constexpr int BU4  = COUT * 12;     // uint4 per B chunk
    constexpr int BBUF = BU4 * 16;      // bytes per B chunk

    extern __shared__ char smem_raw[];
    const uint32_t sAU = smem_u32(smem_raw);              // 4 A tiles
    const uint32_t sBU = sAU + 4 * ABUF;                  // 2 B tiles
    int4* sIdx = reinterpret_cast<int4*>(smem_raw + 4 * ABUF + 2 * BBUF);

    const int tid = threadIdx.x;
    const int wid = tid >> 5, lane = tid & 31;
    const int wm = wid & 3, wn = wid >> 2;
    const int bb = blockIdx.y;
    const int e0 = blockIdx.x * 128;
    const float* xb = x + (size_t)bb * E * CIN;

    for (int i = tid; i < 128; i += 256) sIdx[i] = gemm[e0 + i];
    // zero the padding k-columns (bytes [80,96) of each row) of all 4 A buffers
    for (int i = tid; i < 4 * 128; i += 256)
        STS128Z(sAU + (uint32_t)(i >> 7) * ABUF + (uint32_t)(i & 127) * PITCH + 80);

    const int cc = tid & 7;        // channel-in-chunk
    const int elb = tid >> 3;      // edge base (0..31), items at elb+32q

    float acc[2][NA][4];
#pragma unroll
    for (int ma = 0; ma < 2; ma++)
#pragma unroll
        for (int na = 0; na < NA; na++)
#pragma unroll
            for (int u = 0; u < 4; u++) acc[ma][na][u] = 0.f;

    const uint4* wb4 = reinterpret_cast<const uint4*>(Wb);

    auto stageB = [&](int chunk) {
        const uint32_t dst = sBU + (uint32_t)(chunk & 1) * BBUF;
        const uint4* src = wb4 + (size_t)chunk * BU4;
#pragma unroll
        for (int i = tid; i < BU4; i += 256)
            CPASYNC16(dst + (uint32_t)i * 16, src + i);
        CPCOMMIT();
    };

    // prologue: B_0 in flight
    stageB(0);

    float g[4][5];
    auto gather = [&](int chunk) {
        const float* xc = xb + chunk * 8 + cc;
        float2 mr = make_float2(0.f, 1.f);
        if constexpr (NORM) mr = mstat[bb * CIN + chunk * 8 + cc];
#pragma unroll
        for (int q = 0; q < 4; q++) {
            int el = elb + 32 * q;
            int4 n = sIdx[el];
            float xe = xc[(size_t)(e0 + el) * CIN];
            float f1 = xc[(size_t)n.x * CIN];
            float f2 = xc[(size_t)n.y * CIN];
            float f3 = xc[(size_t)n.z * CIN];
            float f4 = xc[(size_t)n.w * CIN];
            if constexpr (NORM) {
                xe = fmaxf((xe - mr.x) * mr.y, 0.f);
                f1 = fmaxf((f1 - mr.x) * mr.y, 0.f);
                f2 = fmaxf((f2 - mr.x) * mr.y, 0.f);
                f3 = fmaxf((f3 - mr.x) * mr.y, 0.f);
                f4 = fmaxf((f4 - mr.x) * mr.y, 0.f);
            }
            g[q][0] = xe;
            g[q][1] = f1 + f3;  g[q][2] = f2 + f4;
            g[q][3] = fabsf(f1 - f3);  g[q][4] = fabsf(f2 - f4);
        }
    };

    __syncthreads();   // sIdx + padding ready
    gather(0);

    for (int chunk = 0; chunk < CHUNKS; chunk++) {
        const uint32_t bufHi = sAU + (uint32_t)((chunk & 1) * 2) * ABUF;
        const uint32_t bufLo = bufHi + ABUF;
        // ---- commit prefetched gathers: value (cc,s) at byte s*16 + cc*2 ----
#pragma unroll
        for (int q = 0; q < 4; q++) {
            int el = elb + 32 * q;
            uint32_t base = (uint32_t)el * PITCH + (uint32_t)cc * 2;
#pragma unroll
            for (int s = 0; s < 5; s++) {
                __nv_bfloat16 h = __float2bfloat16(g[q][s]);
                STS16(bufHi + base + s * 16, bfbits(h));
                STS16(bufLo + base + s * 16,
                      bfbits(__float2bfloat16(g[q][s] - __bfloat162float(h))));
            }
        }
        // ---- B(chunk) landed (committed last iteration / prologue) ----
        CPWAIT0();
        __syncthreads();   // A stores + B cp.async visible; mma(chunk-1) done
        // ---- stage next B chunk (overwrites buf read by mma(chunk-1): safe
        //      now, the barrier above ordered those reads first) ----
        if (chunk + 1 < CHUNKS) stageB(chunk + 1);
        // ---- prefetch next chunk's gathers (latency hidden by mma below) ----
        if (chunk + 1 < CHUNKS) gather(chunk + 1);
        // ---- ldmatrix + mma (B from smem) ----
        const uint32_t bB = sBU + (uint32_t)(chunk & 1) * BBUF;
#pragma unroll
        for (int ka = 0; ka < 3; ka++) {
            uint32_t ah[2][4], al[2][4];
#pragma unroll
            for (int ma = 0; ma < 2; ma++) {
                uint32_t off = (uint32_t)(wm * 32 + ma * 16 + (lane & 15)) * PITCH
                             + (uint32_t)ka * 32 + ((lane >> 4) * 16);
                LDMX4(ah[ma], bufHi + off);
                LDMX4(al[ma], bufLo + off);
            }
#pragma unroll
            for (int na = 0; na < NA; na++) {
                uint32_t wx, wy, wz, ww;
                LDS128(wx, wy, wz, ww,
                       bB + (uint32_t)(((wn * NA + na) * 3 + ka) * 32 + lane) * 16);
#pragma unroll
                for (int ma = 0; ma < 2; ma++) {
                    MMA16816(acc[ma][na], ah[ma], wx, wy);
                    MMA16816(acc[ma][na], al[ma], wx, wy);
                    MMA16816(acc[ma][na], ah[ma], wz, ww);
                }
            }
        }
    }

    // ---- epilogue: acc + bias -> out ----
    const int rbase = e0 + wm * 32 + (lane >> 2);
#pragma unroll
    for (int ma = 0; ma < 2; ma++) {
#pragma unroll
        for (int na = 0; na < NA; na++) {
            int col = wn * NA * 8 + na * 8 + (lane & 3) * 2;
            float bx = bias[col], by = bias[col + 1];
            int row0 = rbase + ma * 16;
            float* p0 = out + ((size_t)bb * E + row0) * COUT + col;
            float* p1 = p0 + (size_t)8 * COUT;
            *reinterpret_cast<float2*>(p0) =
                make_float2(acc[ma][na][0] + bx, acc[ma][na][1] + by);
            *reinterpret_cast<float2*>(p1) =
                make_float2(acc[ma][na][2] + bx, acc[ma][na][3] + by);
        }
    }
}

// ---------------------------------------------------------------------------
// Small-Cout mesh-conv (COUT = 8), fp32, optional fused inorm+relu on input
// ---------------------------------------------------------------------------
template<int CIN, bool NORM>
__global__ __launch_bounds__(256) void conv_small(
    const float* __restrict__ x, const int4* __restrict__ gemm,
    const float* __restrict__ Wt, const float2* __restrict__ mstat,
    const float* __restrict__ bias, float* __restrict__ out, int E)
{
    constexpr int K = CIN * 5;
    __shared__ float sW[K * 8];
    __shared__ float2 sM[CIN];
    int tid = threadIdx.x;
    int bb = blockIdx.y;
    for (int i = tid; i < K * 8; i += 256) sW[i] = Wt[i];
    if (NORM && tid < CIN) sM[tid] = mstat[bb * CIN + tid];
    float acc[8];
#pragma unroll
    for (int o = 0; o < 8; o++) acc[o] = bias[o];
    __syncthreads();

    int e = blockIdx.x * 256 + tid;
    int4 n = gemm[e];
    const float* xb = x + (size_t)bb * E * CIN;
    const float4* r0 = reinterpret_cast<const float4*>(xb + (size_t)e * CIN);
    const float4* r1 = reinterpret_cast<const float4*>(xb + (size_t)n.x * CIN);
    const float4* r2 = reinterpret_cast<const float4*>(xb + (size_t)n.y * CIN);
    const float4* r3 = reinterpret_cast<const float4*>(xb + (size_t)n.z * CIN);
    const float4* r4 = reinterpret_cast<const float4*>(xb + (size_t)n.w * CIN);

#pragma unroll 2
    for (int c4 = 0; c4 < CIN / 4; c4++) {
        float4 xe = r0[c4], a1 = r1[c4], a2 = r2[c4], a3 = r3[c4], a4 = r4[c4];
#define PROC(COMP, CC)                                                         \
        {                                                                      \
            float xv = xe.COMP, v1 = a1.COMP, v2 = a2.COMP,                    \
                  v3 = a3.COMP, v4 = a4.COMP;                                  \
            if constexpr (NORM) {                                              \
                float2 mm = sM[c4 * 4 + CC];                                   \
                xv = fmaxf((xv - mm.x) * mm.y, 0.f);                           \
                v1 = fmaxf((v1 - mm.x) * mm.y, 0.f);                           \
                v2 = fmaxf((v2 - mm.x) * mm.y, 0.f);                           \
                v3 = fmaxf((v3 - mm.x) * mm.y, 0.f);                           \
                v4 = fmaxf((v4 - mm.x) * mm.y, 0.f);                           \
            }                                                                  \
            float g0 = xv;                                                     \
            float s1 = v1 + v3;                                                \
            float s2 = v2 + v4;                                                \
            float d1 = fabsf(v1 - v3);                                         \
            float d2 = fabsf(v2 - v4);                                         \
            const float* w = &sW[(c4 * 4 + CC) * 5 * 8];                       \
            for (int o = 0; o < 8; o++)                                        \
                acc[o] += g0 * w[o] + s1 * w[8 + o] + s2 * w[16 + o]           \
                        + d1 * w[24 + o] + d2 * w[32 + o];                     \
        }
        PROC(x, 0) PROC(y, 1) PROC(z, 2) PROC(w, 3)
#undef PROC
    }
    float* po = out + ((size_t)bb * E + e) * 8;
    *reinterpret_cast<float4*>(po)     = make_float4(acc[0], acc[1], acc[2], acc[3]);
    *reinterpret_cast<float4*>(po + 4) = make_float4(acc[4], acc[5], acc[6], acc[7]);
}

// ---------------------------------------------------------------------------
// unpool + skip
// ---------------------------------------------------------------------------
template<int C>
__global__ __launch_bounds__(256) void unpool_skip(
    const float* __restrict__ up, const int* __restrict__ unpool,
    const float* __restrict__ skip, float* __restrict__ out,
    int Eout, int Ein)
{
    constexpr int TE = 32;
    __shared__ float ssk[C][TE + 1];
    __shared__ int su[TE];
    int tid = threadIdx.x;
    int bb = blockIdx.y;
    int e0 = blockIdx.x * TE;
    if (tid < TE) su[tid] = unpool[e0 + tid];
    const float* skb = skip + (size_t)bb * C * Eout;
    for (int i = tid; i < C * TE; i += 256) {
        int c = i >> 5, e = i & 31;
        ssk[c][e] = skb[(size_t)c * Eout + e0 + e];
    }
    __syncthreads();
    const float* upb = up + (size_t)bb * Ein * C;
    float* ob = out + ((size_t)bb * Eout + e0) * C;
    for (int i = tid; i < C * TE; i += 256) {
        int el = i / C, c = i % C;
        ob[(size_t)el * C + c] = upb[(size_t)su[el] * C + c] + ssk[c][el];
    }
}

// ---------------------------------------------------------------------------
// Instance norm: partial stats + finalize
// ---------------------------------------------------------------------------
template<int C, int CHUNK>
__global__ __launch_bounds__(256) void inorm_partial(
    const float* __restrict__ x, int E, double* __restrict__ stats)
{
    constexpr int C4 = C / 4;
    constexpr int ESTEP = 256 / C4;
    __shared__ float rb[256][8];
    int tid = threadIdx.x;
    int c4 = tid % C4, er = tid / C4;
    int bb = blockIdx.z;
    int e0 = blockIdx.x * CHUNK;
    const float4* xb4 = reinterpret_cast<const float4*>(x + ((size_t)bb * E + e0) * C) + c4;
    float s0 = 0, s1 = 0, s2 = 0, s3 = 0, q0 = 0, q1 = 0, q2 = 0, q3 = 0;
    for (int e = er; e < CHUNK; e += ESTEP) {
        float4 v = xb4[(size_t)e * C4];
        s0 += v.x; q0 += v.x * v.x;
        s1 += v.y; q1 += v.y * v.y;
        s2 += v.z; q2 += v.z * v.z;
        s3 += v.w; q3 += v.w * v.w;
    }
    rb[tid][0] = s0; rb[tid][1] = s1; rb[tid][2] = s2; rb[tid][3] = s3;
    rb[tid][4] = q0; rb[tid][5] = q1; rb[tid][6] = q2; rb[tid][7] = q3;
    __syncthreads();
    for (int st = ESTEP / 2; st >= 1; st >>= 1) {
        if (er < st) {
#pragma unroll
            for (int u = 0; u < 8; u++) rb[tid][u] += rb[tid + st * C4][u];
        }
        __syncthreads();
    }
    if (er == 0) {
#pragma unroll
        for (int u = 0; u < 4; u++) {
            atomicAdd(&stats[((size_t)bb * C + c4 * 4 + u) * 2],     (double)rb[tid][u]);
            atomicAdd(&stats[((size_t)bb * C + c4 * 4 + u) * 2 + 1], (double)rb[tid][4 + u]);
        }
    }
}

__global__ void finalize_stats(const double* __restrict__ stats,
                               float2* __restrict__ mstat, int n, int E)
{
    int i = threadIdx.x;
    if (i >= n) return;
    double invE = 1.0 / (double)E;
    double m = stats[2 * i] * invE;
    double var = stats[2 * i + 1] * invE - m * m;
    mstat[i] = make_float2((float)m, rsqrtf((float)var + 1e-5f));
}

// Final: reads (B,E,8), writes d_out (B,8,E) with norm+relu, smem transpose.
__global__ __launch_bounds__(256) void inorm_apply_final(
    const float* __restrict__ x, int E, const float2* __restrict__ mstat,
    float* __restrict__ out)
{
    __shared__ float sm[256];
    int tid = threadIdx.x;
    int bb = blockIdx.y;
    int e0 = blockIdx.x * 32;
    float2 mr = mstat[bb * 8 + (tid & 7)];
    float v = (x[((size_t)bb * E + e0) * 8 + tid] - mr.x) * mr.y;
    sm[tid] = v > 0.f ? v : 0.f;
    __syncthreads();
    int c = tid >> 5, el = tid & 31;
    out[((size_t)bb * 8 + c) * E + e0 + el] = sm[el * 8 + c];
}

// ---------------------------------------------------------------------------
// Host driver
// ---------------------------------------------------------------------------
extern "C" void kernel_launch(void* const* d_in, const int* in_sizes, int n_in,
                              void* d_out, int out_size)
{
    (void)in_sizes; (void)n_in; (void)out_size;
    const int E0 = 16384, E1 = 32768, E2 = 65536, E3 = 131072;

    const float* fe    = (const float*)d_in[0];
    const float* skip0 = (const float*)d_in[1];
    const float* skip1 = (const float*)d_in[2];
    const float* skip2 = (const float*)d_in[3];
    const int4*  gm0   = (const int4*)d_in[4];
    const int4*  gm1   = (const int4*)d_in[5];
    const int4*  gm2   = (const int4*)d_in[6];
    const int4*  gm3   = (const int4*)d_in[7];
    const int*   up0   = (const int*)d_in[8];
    const int*   up1   = (const int*)d_in[9];
    const int*   up2   = (const int*)d_in[10];
    const float* Wup0 = (const float*)d_in[11]; const float* bup0 = (const float*)d_in[12];
    const float* Wc0  = (const float*)d_in[13]; const float* bc0  = (const float*)d_in[14];
    const float* Wup1 = (const float*)d_in[15]; const float* bup1 = (const float*)d_in[16];
    const float* Wc1  = (const float*)d_in[17]; const float* bc1  = (const float*)d_in[18];
    const float* Wup2 = (const float*)d_in[19]; const float* bup2 = (const float*)d_in[20];
    const float* Wc2  = (const float*)d_in[21]; const float* bc2  = (const float*)d_in[22];
    const float* Wupf = (const float*)d_in[23]; const float* bupf = (const float*)d_in[24];
    const float* Wcf  = (const float*)d_in[25]; const float* bcf  = (const float*)d_in[26];
    float* outp = (float*)d_out;

    float *bufA, *bufB, *bufU, *bufY, *wt; double* stats; float2* mstat;
    __nv_bfloat16 *wb;
    cudaGetSymbolAddress((void**)&bufA, g_bufA);
    cudaGetSymbolAddress((void**)&bufB, g_bufB);
    cudaGetSymbolAddress((void**)&bufU, g_bufU);
    cudaGetSymbolAddress((void**)&bufY, g_bufY);
    cudaGetSymbolAddress((void**)&wt,   g_wt);
    cudaGetSymbolAddress((void**)&wb,   g_wb);
    cudaGetSymbolAddress((void**)&stats, g_stats);
    cudaGetSymbolAddress((void**)&mstat, g_mstat);

    float* Wt_upf = wt + 322560;
    float* Wt_cf  = wt + 323840;

    // wb offsets (bf16 units)
    __nv_bfloat16* Wb_up0 = wb;
    __nv_bfloat16* Wb_c0  = wb + 393216;
    __nv_bfloat16* Wb_up1 = wb + 589824;
    __nv_bfloat16* Wb_c1  = wb + 688128;
    __nv_bfloat16* Wb_up2 = wb + 737280;
    __nv_bfloat16* Wb_c2  = wb + 761856;

    double* stats0 = stats;
    double* stats1 = stats + 512;
    double* stats2 = stats + 768;
    double* statsF = stats + 896;
    float2* mst0 = mstat;
    float2* mst1 = mstat + 256;
    float2* mst2 = mstat + 384;
    float2* mstF = mstat + 448;

    // dynamic smem: 4 A tiles + 2 B tiles + idx
    const int SM128 = 4 * 14336 + 2 * 128 * 192 + 2048;   // 108544
    const int SM64  = 4 * 14336 + 2 * 64 * 192 + 2048;    //  83968
    const int SM32  = 4 * 14336 + 2 * 32 * 192 + 2048;    //  71680
    cudaFuncSetAttribute(conv_t<256, 128, false>, cudaFuncAttributeMaxDynamicSharedMemorySize, SM128);
    cudaFuncSetAttribute(conv_t<128, 128, false>, cudaFuncAttributeMaxDynamicSharedMemorySize, SM128);
    cudaFuncSetAttribute(conv_t<128, 64, true>,   cudaFuncAttributeMaxDynamicSharedMemorySize, SM64);
    cudaFuncSetAttribute(conv_t<64, 64, false>,   cudaFuncAttributeMaxDynamicSharedMemorySize, SM64);
    cudaFuncSetAttribute(conv_t<64, 32, true>,    cudaFuncAttributeMaxDynamicSharedMemorySize, SM32);
    cudaFuncSetAttribute(conv_t<32, 32, false>,   cudaFuncAttributeMaxDynamicSharedMemorySize, SM32);

    // launches: wtrans+zero(0), wbf48(1), xpose(2), conv_t up0(3 = ncu target)
    wtrans_all<<<1267, 256>>>(Wup0, Wc0, Wup1, Wc1, Wup2, Wc2, Wupf, Wcf, wt, stats);
    wbf48<<<3024, 256>>>(Wup0, Wc0, Wup1, Wc1, Wup2, Wc2, wb);
    xpose<<<dim3(E0 / 32, 256 / 32, 2), dim3(32, 8)>>>(fe, bufA, E0, 256);

    // ---- Level 0 ----
    conv_t<256, 128, false><<<dim3(E0 / 128, 2), 256, SM128>>>(bufA, gm0, Wb_up0, nullptr, bup0, bufU, E0);
    unpool_skip<128><<<dim3(E1 / 32, 2), 256>>>(bufU, up0, skip0, bufY, E1, E0);
    conv_t<128, 128, false><<<dim3(E1 / 128, 2), 256, SM128>>>(bufY, gm1, Wb_c0, nullptr, bc0, bufB, E1);
    inorm_partial<128, 256><<<dim3(E1 / 256, 1, 2), 256>>>(bufB, E1, stats0);
    finalize_stats<<<1, 256>>>(stats0, mst0, 256, E1);

    // ---- Level 1 ---- (up1 consumes bufB with fused norm+relu)
    conv_t<128, 64, true><<<dim3(E1 / 128, 2), 256, SM64>>>(bufB, gm1, Wb_up1, mst0, bup1, bufU, E1);
    unpool_skip<64><<<dim3(E2 / 32, 2), 256>>>(bufU, up1, skip1, bufY, E2, E1);
    conv_t<64, 64, false><<<dim3(E2 / 128, 2), 256, SM64>>>(bufY, gm2, Wb_c1, nullptr, bc1, bufA, E2);
    inorm_partial<64, 512><<<dim3(E2 / 512, 1, 2), 256>>>(bufA, E2, stats1);
    finalize_stats<<<1, 128>>>(stats1, mst1, 128, E2);

    // ---- Level 2 ---- (up2 consumes bufA with fused norm+relu)
    conv_t<64, 32, true><<<dim3(E2 / 128, 2), 256, SM32>>>(bufA, gm2, Wb_up2, mst1, bup2, bufU, E2);
    unpool_skip<32><<<dim3(E3 / 32, 2), 256>>>(bufU, up2, skip2, bufY, E3, E2);
    conv_t<32, 32, false><<<dim3(E3 / 128, 2), 256, SM32>>>(bufY, gm3, Wb_c2, nullptr, bc2, bufB, E3);
    inorm_partial<32, 1024><<<dim3(E3 / 1024, 1, 2), 256>>>(bufB, E3, stats2);
    finalize_stats<<<1, 64>>>(stats2, mst2, 64, E3);

    // ---- Final ---- (upf consumes bufB with fused norm+relu)
    conv_small<32, true><<<dim3(E3 / 256, 2), 256>>>(bufB, gm3, Wt_upf, mst2, bupf, bufU, E3);
    conv_small<8, false><<<dim3(E3 / 256, 2), 256>>>(bufU, gm3, Wt_cf, nullptr, bcf, bufY, E3);
    inorm_partial<8, 4096><<<dim3(E3 / 4096, 1, 2), 256>>>(bufY, E3, statsF);
    finalize_stats<<<1, 16>>>(statsF, mstF, 16, E3);
    inorm_apply_final<<<dim3(E3 / 32, 2), 256>>>(bufY, E3, mstF, outp);
}